// round 2
// baseline (speedup 1.0000x reference)
#include <cuda_runtime.h>
#include <math.h>

// Problem constants (fixed by the dataset)
#define NMAX 100000
#define EMAX 800000
#define HCD  128     // H*C = 4*32
#define NH   4       // heads

// ---------------- scratch (device globals; no allocation allowed) ----------
__device__ float g_Q [(size_t)NMAX * HCD];
__device__ float g_K [(size_t)NMAX * HCD];
__device__ float g_V [(size_t)NMAX * HCD];
__device__ float g_Ha[(size_t)NMAX * HCD];   // layer0 output accumulator
__device__ float g_Hb[(size_t)NMAX * HCD];   // layer1 output accumulator
__device__ float g_alpha[(size_t)EMAX * NH]; // per-edge logits -> exp values
__device__ float g_m  [NMAX * NH];           // segment max
__device__ float g_den[NMAX * NH];           // segment sum
__device__ int   g_src[EMAX];
__device__ int   g_dst[EMAX];

// ---------------- helpers ---------------------------------------------------
__device__ __forceinline__ void atomicMaxF(float* addr, float val) {
    int* ia = (int*)addr;
    int old = *ia;
    while (__int_as_float(old) < val) {
        int assumed = old;
        old = atomicCAS(ia, assumed, __float_as_int(val));
        if (old == assumed) break;
    }
}

__device__ __forceinline__ void redAddV4(float* addr, float4 r) {
    asm volatile("red.global.add.v4.f32 [%0], {%1, %2, %3, %4};"
                 :: "l"(addr), "f"(r.x), "f"(r.y), "f"(r.z), "f"(r.w)
                 : "memory");
}

// ---------------- edge_index normalization (handles int32 OR int64) --------
// int64 little-endian: element i occupies words [2i, 2i+1]; indices < 2^31 so
// every odd word is 0. int32 random indices: odd words are ~never all zero.
__global__ void convert_ei_kernel(const int* __restrict__ p, int E,
                                  int* __restrict__ src, int* __restrict__ dst) {
    __shared__ int s_is64;
    if (threadIdx.x == 0) {
        int is64 = 1;
        for (int i = 0; i < 64; i++)
            if (p[2 * i + 1] != 0) { is64 = 0; break; }
        s_is64 = is64;
    }
    __syncthreads();
    const int is64 = s_is64;
    int e = blockIdx.x * blockDim.x + threadIdx.x;
    if (e >= E) return;
    if (is64) {
        src[e] = p[2 * e];
        dst[e] = p[2 * (E + e)];
    } else {
        src[e] = p[e];
        dst[e] = p[E + e];
    }
}

// ---------------- layer-0 projection (input dim = 2) -----------------------
__global__ void proj0_kernel(const float* __restrict__ x,
                             const float* __restrict__ Wq, const float* __restrict__ bq,
                             const float* __restrict__ Wk, const float* __restrict__ bk,
                             const float* __restrict__ Wv, const float* __restrict__ bv,
                             const float* __restrict__ Ws, const float* __restrict__ bs,
                             float* __restrict__ Q, float* __restrict__ K,
                             float* __restrict__ V, float* __restrict__ S, int n) {
    int i = blockIdx.x * blockDim.x + threadIdx.x;
    if (i >= n * HCD) return;
    int node = i >> 7;
    int c    = i & (HCD - 1);
    float x0 = __ldg(&x[node * 2 + 0]);
    float x1 = __ldg(&x[node * 2 + 1]);
    Q[i] = fmaf(x0, __ldg(&Wq[c]), fmaf(x1, __ldg(&Wq[HCD + c]), __ldg(&bq[c])));
    K[i] = fmaf(x0, __ldg(&Wk[c]), fmaf(x1, __ldg(&Wk[HCD + c]), __ldg(&bk[c])));
    V[i] = fmaf(x0, __ldg(&Wv[c]), fmaf(x1, __ldg(&Wv[HCD + c]), __ldg(&bv[c])));
    S[i] = fmaf(x0, __ldg(&Ws[c]), fmaf(x1, __ldg(&Ws[HCD + c]), __ldg(&bs[c])));
}

// ---------------- generic fp32 GEMM: Y[n,NC] = op(X[n,KD]) @ W[KD,NC] + b ---
template<int KD, int NC, bool RIN, bool ROUT>
__global__ __launch_bounds__(256)
void gemm_kernel(const float* __restrict__ X, const float* __restrict__ W,
                 const float* __restrict__ bias, float* __restrict__ Y, int n) {
    __shared__ float Xs[64 * KD];
    const int tid = threadIdx.x;
    const int node0 = blockIdx.x * 64;

    for (int idx = tid; idx < 64 * KD; idx += 256) {
        int r = idx / KD;
        int k = idx - r * KD;
        int node = node0 + r;
        float v = 0.f;
        if (node < n) {
            v = X[(size_t)node * KD + k];
            if (RIN) v = fmaxf(v, 0.f);
        }
        Xs[idx] = v;
    }
    __syncthreads();

    constexpr int CPT = NC / 16;          // cols per thread
    const int cg = tid & 15;
    const int ng = tid >> 4;
    const int c0 = cg * CPT;

    float acc[4][CPT];
#pragma unroll
    for (int i = 0; i < 4; i++)
#pragma unroll
        for (int j = 0; j < CPT; j++) acc[i][j] = __ldg(&bias[c0 + j]);

    const float* xp = &Xs[(ng * 4) * KD];
#pragma unroll 4
    for (int k = 0; k < KD; k++) {
        float a0 = xp[k], a1 = xp[KD + k], a2 = xp[2 * KD + k], a3 = xp[3 * KD + k];
        float wv[CPT];
#pragma unroll
        for (int j4 = 0; j4 < CPT / 4; j4++) {
            float4 w4 = __ldg((const float4*)(W + (size_t)k * NC + c0) + j4);
            wv[j4 * 4 + 0] = w4.x; wv[j4 * 4 + 1] = w4.y;
            wv[j4 * 4 + 2] = w4.z; wv[j4 * 4 + 3] = w4.w;
        }
#pragma unroll
        for (int j = 0; j < CPT; j++) {
            acc[0][j] = fmaf(a0, wv[j], acc[0][j]);
            acc[1][j] = fmaf(a1, wv[j], acc[1][j]);
            acc[2][j] = fmaf(a2, wv[j], acc[2][j]);
            acc[3][j] = fmaf(a3, wv[j], acc[3][j]);
        }
    }

#pragma unroll
    for (int i = 0; i < 4; i++) {
        int node = node0 + ng * 4 + i;
        if (node < n) {
#pragma unroll
            for (int j = 0; j < CPT; j += 4) {
                float4 o;
                o.x = acc[i][j];     o.y = acc[i][j + 1];
                o.z = acc[i][j + 2]; o.w = acc[i][j + 3];
                if (ROUT) {
                    o.x = fmaxf(o.x, 0.f); o.y = fmaxf(o.y, 0.f);
                    o.z = fmaxf(o.z, 0.f); o.w = fmaxf(o.w, 0.f);
                }
                *(float4*)(Y + (size_t)node * NC + c0 + j) = o;
            }
        }
    }
}

// ---------------- init segment buffers -------------------------------------
__global__ void init_seg_kernel(float* __restrict__ m, float* __restrict__ den, int total) {
    int i = blockIdx.x * blockDim.x + threadIdx.x;
    if (i >= total) return;
    m[i]   = -INFINITY;
    den[i] = 0.f;
}

// ---------------- edge pass 1: logits + segment max (warp per edge) --------
__global__ __launch_bounds__(256)
void edge_alpha_kernel(const int* __restrict__ srcArr, const int* __restrict__ dstArr,
                       const float* __restrict__ ea,
                       const float* __restrict__ Q, const float* __restrict__ K,
                       const float* __restrict__ We,
                       float* __restrict__ alpha, float* __restrict__ m, int E) {
    int e = (blockIdx.x * blockDim.x + threadIdx.x) >> 5;
    int lane = threadIdx.x & 31;
    if (e >= E) return;

    int src   = __ldg(&srcArr[e]);
    int dst   = __ldg(&dstArr[e]);
    float eat = __ldg(&ea[e]);

    int c0 = lane * 4;
    float4 q = *(const float4*)(Q + (size_t)dst * HCD + c0);
    float4 k = *(const float4*)(K + (size_t)src * HCD + c0);
    float4 w = *(const float4*)(We + c0);

    float p = q.x * fmaf(eat, w.x, k.x)
            + q.y * fmaf(eat, w.y, k.y)
            + q.z * fmaf(eat, w.z, k.z)
            + q.w * fmaf(eat, w.w, k.w);
    p += __shfl_xor_sync(0xffffffffu, p, 1);
    p += __shfl_xor_sync(0xffffffffu, p, 2);
    p += __shfl_xor_sync(0xffffffffu, p, 4);

    if ((lane & 7) == 0) {
        int h = lane >> 3;
        float a = p * 0.17677669529663687f;   // 1/sqrt(32)
        alpha[(size_t)e * NH + h] = a;
        atomicMaxF(&m[dst * NH + h], a);
    }
}

// ---------------- edge pass 2: exp + segment sum (thread per edge*head) ----
__global__ void edge_softmax_kernel(const int* __restrict__ dstArr,
                                    float* __restrict__ alpha,
                                    const float* __restrict__ m,
                                    float* __restrict__ den, int E) {
    int i = blockIdx.x * blockDim.x + threadIdx.x;
    if (i >= E * NH) return;
    int e = i >> 2;
    int h = i & (NH - 1);
    int dst = __ldg(&dstArr[e]);
    float ex = expf(alpha[i] - m[dst * NH + h]);
    alpha[i] = ex;
    atomicAdd(&den[dst * NH + h], ex);
}

// ---------------- edge pass 3: weighted scatter (warp per edge) ------------
__global__ __launch_bounds__(256)
void edge_aggr_kernel(const int* __restrict__ srcArr, const int* __restrict__ dstArr,
                      const float* __restrict__ ea,
                      const float* __restrict__ V, const float* __restrict__ We,
                      const float* __restrict__ alpha, const float* __restrict__ den,
                      float* __restrict__ Hout, int E) {
    int e = (blockIdx.x * blockDim.x + threadIdx.x) >> 5;
    int lane = threadIdx.x & 31;
    if (e >= E) return;

    int src   = __ldg(&srcArr[e]);
    int dst   = __ldg(&dstArr[e]);
    float eat = __ldg(&ea[e]);

    int c0 = lane * 4;
    int h  = lane >> 3;
    float ex = __ldg(&alpha[(size_t)e * NH + h]);
    float dn = __ldg(&den[dst * NH + h]);
    float wgt = ex / (dn + 1e-16f);

    float4 v = *(const float4*)(V + (size_t)src * HCD + c0);
    float4 w = *(const float4*)(We + c0);
    float4 r;
    r.x = fmaf(eat, w.x, v.x) * wgt;
    r.y = fmaf(eat, w.y, v.y) * wgt;
    r.z = fmaf(eat, w.z, v.z) * wgt;
    r.w = fmaf(eat, w.w, v.w) * wgt;

    redAddV4(Hout + (size_t)dst * HCD + c0, r);
}

// ---------------- final classifier layer: 64 -> 1 --------------------------
__global__ void final_kernel(const float* __restrict__ Z2, const float* __restrict__ Wc3,
                             const float* __restrict__ bc3, float* __restrict__ out, int n) {
    int node = blockIdx.x * blockDim.x + threadIdx.x;
    if (node >= n) return;
    float s = __ldg(&bc3[0]);
    const float4* z = (const float4*)(Z2 + (size_t)node * 64);
#pragma unroll
    for (int j = 0; j < 16; j++) {
        float4 a = z[j];
        float4 w = __ldg((const float4*)Wc3 + j);
        s += a.x * w.x + a.y * w.y + a.z * w.z + a.w * w.w;
    }
    out[node] = s;
}

// ---------------- launch ----------------------------------------------------
extern "C" void kernel_launch(void* const* d_in, const int* in_sizes, int n_in,
                              void* d_out, int out_size) {
    const float* x   = (const float*)d_in[0];
    const int*   eiw = (const int*)d_in[1];      // raw words; width detected on device
    const float* ea  = (const float*)d_in[2];
    const float *Wq0 = (const float*)d_in[3],  *bq0 = (const float*)d_in[4];
    const float *Wk0 = (const float*)d_in[5],  *bk0 = (const float*)d_in[6];
    const float *Wv0 = (const float*)d_in[7],  *bv0 = (const float*)d_in[8];
    const float *We0 = (const float*)d_in[9];
    const float *Ws0 = (const float*)d_in[10], *bs0 = (const float*)d_in[11];
    const float *Wq1 = (const float*)d_in[12], *bq1 = (const float*)d_in[13];
    const float *Wk1 = (const float*)d_in[14], *bk1 = (const float*)d_in[15];
    const float *Wv1 = (const float*)d_in[16], *bv1 = (const float*)d_in[17];
    const float *We1 = (const float*)d_in[18];
    const float *Ws1 = (const float*)d_in[19], *bs1 = (const float*)d_in[20];
    const float *Wc1 = (const float*)d_in[21], *bc1 = (const float*)d_in[22];
    const float *Wc2 = (const float*)d_in[23], *bc2 = (const float*)d_in[24];
    const float *Wc3 = (const float*)d_in[25], *bc3 = (const float*)d_in[26];

    const int n = in_sizes[0] / 2;      // nodes
    const int E = in_sizes[2];          // edges (edge_attr is E x 1)

    float *Q, *K, *V, *Ha, *Hb, *alpha, *m, *den;
    int *src, *dst;
    cudaGetSymbolAddress((void**)&Q,     g_Q);
    cudaGetSymbolAddress((void**)&K,     g_K);
    cudaGetSymbolAddress((void**)&V,     g_V);
    cudaGetSymbolAddress((void**)&Ha,    g_Ha);
    cudaGetSymbolAddress((void**)&Hb,    g_Hb);
    cudaGetSymbolAddress((void**)&alpha, g_alpha);
    cudaGetSymbolAddress((void**)&m,     g_m);
    cudaGetSymbolAddress((void**)&den,   g_den);
    cudaGetSymbolAddress((void**)&src,   g_src);
    cudaGetSymbolAddress((void**)&dst,   g_dst);

    const int TB = 256;
    dim3 edgeGrid((E + 7) / 8);           // 8 warps per block, warp per edge
    dim3 gemmGrid((n + 63) / 64);

    convert_ei_kernel<<<(E + TB - 1) / TB, TB>>>(eiw, E, src, dst);

    // ---------------- layer 0 ----------------
    proj0_kernel<<<(n * HCD + TB - 1) / TB, TB>>>(x, Wq0, bq0, Wk0, bk0, Wv0, bv0,
                                                  Ws0, bs0, Q, K, V, Ha, n);
    init_seg_kernel<<<(n * NH + TB - 1) / TB, TB>>>(m, den, n * NH);
    edge_alpha_kernel  <<<edgeGrid, TB>>>(src, dst, ea, Q, K, We0, alpha, m, E);
    edge_softmax_kernel<<<(E * NH + TB - 1) / TB, TB>>>(dst, alpha, m, den, E);
    edge_aggr_kernel   <<<edgeGrid, TB>>>(src, dst, ea, V, We0, alpha, den, Ha, E);

    // ---------------- layer 1 projections (input = relu(Ha)) ----------------
    gemm_kernel<128, 128, true, false><<<gemmGrid, TB>>>(Ha, Wq1, bq1, Q,  n);
    gemm_kernel<128, 128, true, false><<<gemmGrid, TB>>>(Ha, Wk1, bk1, K,  n);
    gemm_kernel<128, 128, true, false><<<gemmGrid, TB>>>(Ha, Wv1, bv1, V,  n);
    gemm_kernel<128, 128, true, false><<<gemmGrid, TB>>>(Ha, Ws1, bs1, Hb, n);

    init_seg_kernel<<<(n * NH + TB - 1) / TB, TB>>>(m, den, n * NH);
    edge_alpha_kernel  <<<edgeGrid, TB>>>(src, dst, ea, Q, K, We1, alpha, m, E);
    edge_softmax_kernel<<<(E * NH + TB - 1) / TB, TB>>>(dst, alpha, m, den, E);
    edge_aggr_kernel   <<<edgeGrid, TB>>>(src, dst, ea, V, We1, alpha, den, Hb, E);

    // ---------------- classifier (input = relu(Hb)) ----------------
    gemm_kernel<128, 128, true,  true><<<gemmGrid, TB>>>(Hb, Wc1, bc1, Q, n); // Z1
    gemm_kernel<128, 64,  false, true><<<gemmGrid, TB>>>(Q,  Wc2, bc2, K, n); // Z2
    final_kernel<<<(n + TB - 1) / TB, TB>>>(K, Wc3, bc3, (float*)d_out, n);
}

// round 3
// speedup vs baseline: 1.0261x; 1.0261x over previous
#include <cuda_runtime.h>
#include <math.h>

#define NMAX 100000
#define EMAX 800000
#define HCD  128     // H*C = 4*32
#define NH   4       // heads

// ---------------- scratch ----------------------------------------------------
__device__ float g_Q [(size_t)NMAX * HCD];
__device__ float g_K [(size_t)NMAX * HCD];
__device__ float g_V [(size_t)NMAX * HCD];
__device__ float g_Ha[(size_t)NMAX * HCD];
__device__ float g_Hb[(size_t)NMAX * HCD];
__device__ float g_alpha[(size_t)EMAX * NH];
__device__ float g_den[NMAX * NH];
__device__ int   g_src[EMAX];
__device__ int   g_dst[EMAX];

// ---------------- helpers -----------------------------------------------------
__device__ __forceinline__ void redAddV4(float* addr, float4 r) {
    asm volatile("red.global.add.v4.f32 [%0], {%1, %2, %3, %4};"
                 :: "l"(addr), "f"(r.x), "f"(r.y), "f"(r.z), "f"(r.w)
                 : "memory");
}

__device__ __forceinline__ unsigned tf32cvt(float f) {
    unsigned u;
    asm("cvt.rna.tf32.f32 %0, %1;" : "=r"(u) : "f"(f));
    return u;
}

__device__ __forceinline__ void mma_tf32(float* c, const unsigned* a, const unsigned* b) {
    asm volatile(
        "mma.sync.aligned.m16n8k8.row.col.f32.tf32.tf32.f32 "
        "{%0,%1,%2,%3}, {%4,%5,%6,%7}, {%8,%9}, {%0,%1,%2,%3};"
        : "+f"(c[0]), "+f"(c[1]), "+f"(c[2]), "+f"(c[3])
        : "r"(a[0]), "r"(a[1]), "r"(a[2]), "r"(a[3]), "r"(b[0]), "r"(b[1]));
}

// ---------------- edge_index normalization (int32 OR int64) -------------------
__global__ void convert_ei_kernel(const int* __restrict__ p, int E,
                                  int* __restrict__ src, int* __restrict__ dst) {
    __shared__ int s_is64;
    if (threadIdx.x == 0) {
        int is64 = 1;
        for (int i = 0; i < 64; i++)
            if (p[2 * i + 1] != 0) { is64 = 0; break; }
        s_is64 = is64;
    }
    __syncthreads();
    const int is64 = s_is64;
    int e = blockIdx.x * blockDim.x + threadIdx.x;
    if (e >= E) return;
    if (is64) { src[e] = p[2 * e]; dst[e] = p[2 * (E + e)]; }
    else      { src[e] = p[e];     dst[e] = p[E + e]; }
}

// ---------------- layer-0 projection (input dim = 2) --------------------------
__global__ void proj0_kernel(const float* __restrict__ x,
                             const float* __restrict__ Wq, const float* __restrict__ bq,
                             const float* __restrict__ Wk, const float* __restrict__ bk,
                             const float* __restrict__ Wv, const float* __restrict__ bv,
                             const float* __restrict__ Ws, const float* __restrict__ bs,
                             float* __restrict__ Q, float* __restrict__ K,
                             float* __restrict__ V, float* __restrict__ S, int n) {
    int i = blockIdx.x * blockDim.x + threadIdx.x;
    if (i >= n * HCD) return;
    int node = i >> 7;
    int c    = i & (HCD - 1);
    float x0 = __ldg(&x[node * 2 + 0]);
    float x1 = __ldg(&x[node * 2 + 1]);
    Q[i] = fmaf(x0, __ldg(&Wq[c]), fmaf(x1, __ldg(&Wq[HCD + c]), __ldg(&bq[c])));
    K[i] = fmaf(x0, __ldg(&Wk[c]), fmaf(x1, __ldg(&Wk[HCD + c]), __ldg(&bk[c])));
    V[i] = fmaf(x0, __ldg(&Wv[c]), fmaf(x1, __ldg(&Wv[HCD + c]), __ldg(&bv[c])));
    S[i] = fmaf(x0, __ldg(&Ws[c]), fmaf(x1, __ldg(&Ws[HCD + c]), __ldg(&bs[c])));
}

// ---------------- tensor-core GEMM: Y[n,NC] = op(X[n,128]) @ W[128,NC] + b ----
// 64-row tile, 128 threads (4 warps, 16 rows/warp), tf32 mma m16n8k8.
// A and B pre-swizzled into fragment order in dynamic smem (conflict-free LDS).
template<int NC, bool RIN, bool ROUT>
__global__ __launch_bounds__(128)
void gemm_tc(const float* __restrict__ X, const float* __restrict__ W,
             const float* __restrict__ bias, float* __restrict__ Y, int n) {
    constexpr int KD = 128;
    constexpr int KS = KD / 8;      // 16 k-steps
    constexpr int JT = NC / 8;      // n-tiles
    extern __shared__ unsigned smem[];
    unsigned* sA = smem;                       // [4][KS][32][4] = 8192 words
    unsigned* sB = smem + 4 * KS * 32 * 4;     // [KS][JT][32][2]

    const int tid  = threadIdx.x;
    const int node0 = blockIdx.x * 64;

    // ---- fill A (fragment order), with optional input relu ----
    for (int base = tid * 4; base < 64 * KD; base += 128 * 4) {
        int row  = base >> 7;          // 0..63
        int k0   = base & 127;
        int node = node0 + row;
        float4 v = make_float4(0.f, 0.f, 0.f, 0.f);
        if (node < n) v = *(const float4*)(X + (size_t)node * KD + k0);
        if (RIN) {
            v.x = fmaxf(v.x, 0.f); v.y = fmaxf(v.y, 0.f);
            v.z = fmaxf(v.z, 0.f); v.w = fmaxf(v.w, 0.f);
        }
        float vv[4] = {v.x, v.y, v.z, v.w};
        int w = row >> 4, r = row & 15;
#pragma unroll
        for (int i = 0; i < 4; i++) {
            int k = k0 + i, s = k >> 3, kk = k & 7;
            int lane = ((r & 7) << 2) | (kk & 3);
            int ii   = (r >> 3) | ((kk >> 2) << 1);
            sA[(((w * KS + s) * 32) + lane) * 4 + ii] = tf32cvt(vv[i]);
        }
    }
    // ---- fill B (fragment order) ----
    for (int base = tid * 4; base < KD * NC; base += 128 * 4) {
        int k  = base / NC;
        int n0 = base % NC;
        float4 v = *(const float4*)(W + (size_t)k * NC + n0);
        float vv[4] = {v.x, v.y, v.z, v.w};
        int s = k >> 3, kk = k & 7;
#pragma unroll
        for (int i = 0; i < 4; i++) {
            int nn = n0 + i, j = nn >> 3;
            int lane = ((nn & 7) << 2) | (kk & 3);
            int ii   = kk >> 2;
            sB[(((s * JT + j) * 32) + lane) * 2 + ii] = tf32cvt(vv[i]);
        }
    }
    __syncthreads();

    const int wid  = tid >> 5;
    const int lane = tid & 31;

    float acc[JT][4];
#pragma unroll
    for (int j = 0; j < JT; j++) {
        float b0 = __ldg(&bias[j * 8 + (lane & 3) * 2]);
        float b1 = __ldg(&bias[j * 8 + (lane & 3) * 2 + 1]);
        acc[j][0] = b0; acc[j][1] = b1; acc[j][2] = b0; acc[j][3] = b1;
    }

#pragma unroll
    for (int s = 0; s < KS; s++) {
        uint4 av = *(const uint4*)&sA[(((wid * KS + s) * 32) + lane) * 4];
        unsigned a[4] = {av.x, av.y, av.z, av.w};
#pragma unroll
        for (int j = 0; j < JT; j++) {
            uint2 bv = *(const uint2*)&sB[(((s * JT + j) * 32) + lane) * 2];
            unsigned b[2] = {bv.x, bv.y};
            mma_tf32(acc[j], a, b);
        }
    }

    int row0 = node0 + wid * 16 + (lane >> 2);
    int row1 = row0 + 8;
#pragma unroll
    for (int j = 0; j < JT; j++) {
        int col = j * 8 + (lane & 3) * 2;
        float2 o0 = make_float2(acc[j][0], acc[j][1]);
        float2 o1 = make_float2(acc[j][2], acc[j][3]);
        if (ROUT) {
            o0.x = fmaxf(o0.x, 0.f); o0.y = fmaxf(o0.y, 0.f);
            o1.x = fmaxf(o1.x, 0.f); o1.y = fmaxf(o1.y, 0.f);
        }
        if (row0 < n) *(float2*)(Y + (size_t)row0 * NC + col) = o0;
        if (row1 < n) *(float2*)(Y + (size_t)row1 * NC + col) = o1;
    }
}

// ---------------- init den ----------------------------------------------------
__global__ void init_den_kernel(float* __restrict__ den, int total) {
    int i = blockIdx.x * blockDim.x + threadIdx.x;
    if (i < total) den[i] = 0.f;
}

// ---------------- edge pass 1: exp(logit) + segment sum (warp per edge) -------
__global__ __launch_bounds__(256)
void edge_alpha_kernel(const int* __restrict__ srcArr, const int* __restrict__ dstArr,
                       const float* __restrict__ ea,
                       const float* __restrict__ Q, const float* __restrict__ K,
                       const float* __restrict__ We,
                       float* __restrict__ alpha, float* __restrict__ den, int E) {
    int e = (blockIdx.x * blockDim.x + threadIdx.x) >> 5;
    int lane = threadIdx.x & 31;
    if (e >= E) return;

    int src   = __ldg(&srcArr[e]);
    int dst   = __ldg(&dstArr[e]);
    float eat = __ldg(&ea[e]);

    int c0 = lane * 4;
    float4 q = *(const float4*)(Q + (size_t)dst * HCD + c0);
    float4 k = *(const float4*)(K + (size_t)src * HCD + c0);
    float4 w = *(const float4*)(We + c0);

    float p = q.x * fmaf(eat, w.x, k.x)
            + q.y * fmaf(eat, w.y, k.y)
            + q.z * fmaf(eat, w.z, k.z)
            + q.w * fmaf(eat, w.w, k.w);
    p += __shfl_xor_sync(0xffffffffu, p, 1);
    p += __shfl_xor_sync(0xffffffffu, p, 2);
    p += __shfl_xor_sync(0xffffffffu, p, 4);

    float ex = 0.f;
    if ((lane & 7) == 0) ex = expf(p * 0.17677669529663687f);  // 1/sqrt(32)

    float e0 = __shfl_sync(0xffffffffu, ex, 0);
    float e1 = __shfl_sync(0xffffffffu, ex, 8);
    float e2 = __shfl_sync(0xffffffffu, ex, 16);
    float e3 = __shfl_sync(0xffffffffu, ex, 24);
    if (lane == 0) {
        float4 r = make_float4(e0, e1, e2, e3);
        *(float4*)(alpha + (size_t)e * NH) = r;
        redAddV4(&den[dst * NH], r);
    }
}

// ---------------- edge pass 2: weighted scatter (warp per edge) ---------------
__global__ __launch_bounds__(256)
void edge_aggr_kernel(const int* __restrict__ srcArr, const int* __restrict__ dstArr,
                      const float* __restrict__ ea,
                      const float* __restrict__ V, const float* __restrict__ We,
                      const float* __restrict__ alpha, const float* __restrict__ den,
                      float* __restrict__ Hout, int E) {
    int e = (blockIdx.x * blockDim.x + threadIdx.x) >> 5;
    int lane = threadIdx.x & 31;
    if (e >= E) return;

    int src   = __ldg(&srcArr[e]);
    int dst   = __ldg(&dstArr[e]);
    float eat = __ldg(&ea[e]);

    int c0 = lane * 4;
    int h  = lane >> 3;
    float ex = __ldg(&alpha[(size_t)e * NH + h]);
    float dn = __ldg(&den[dst * NH + h]);
    float wgt = ex / (dn + 1e-16f);

    float4 v = *(const float4*)(V + (size_t)src * HCD + c0);
    float4 w = *(const float4*)(We + c0);
    float4 r;
    r.x = fmaf(eat, w.x, v.x) * wgt;
    r.y = fmaf(eat, w.y, v.y) * wgt;
    r.z = fmaf(eat, w.z, v.z) * wgt;
    r.w = fmaf(eat, w.w, v.w) * wgt;

    redAddV4(Hout + (size_t)dst * HCD + c0, r);
}

// ---------------- final classifier layer: 64 -> 1 ------------------------------
__global__ void final_kernel(const float* __restrict__ Z2, const float* __restrict__ Wc3,
                             const float* __restrict__ bc3, float* __restrict__ out, int n) {
    int node = blockIdx.x * blockDim.x + threadIdx.x;
    if (node >= n) return;
    float s = __ldg(&bc3[0]);
    const float4* z = (const float4*)(Z2 + (size_t)node * 64);
#pragma unroll
    for (int j = 0; j < 16; j++) {
        float4 a = z[j];
        float4 w = __ldg((const float4*)Wc3 + j);
        s += a.x * w.x + a.y * w.y + a.z * w.z + a.w * w.w;
    }
    out[node] = s;
}

// ---------------- launch --------------------------------------------------------
extern "C" void kernel_launch(void* const* d_in, const int* in_sizes, int n_in,
                              void* d_out, int out_size) {
    const float* x   = (const float*)d_in[0];
    const int*   eiw = (const int*)d_in[1];
    const float* ea  = (const float*)d_in[2];
    const float *Wq0 = (const float*)d_in[3],  *bq0 = (const float*)d_in[4];
    const float *Wk0 = (const float*)d_in[5],  *bk0 = (const float*)d_in[6];
    const float *Wv0 = (const float*)d_in[7],  *bv0 = (const float*)d_in[8];
    const float *We0 = (const float*)d_in[9];
    const float *Ws0 = (const float*)d_in[10], *bs0 = (const float*)d_in[11];
    const float *Wq1 = (const float*)d_in[12], *bq1 = (const float*)d_in[13];
    const float *Wk1 = (const float*)d_in[14], *bk1 = (const float*)d_in[15];
    const float *Wv1 = (const float*)d_in[16], *bv1 = (const float*)d_in[17];
    const float *We1 = (const float*)d_in[18];
    const float *Ws1 = (const float*)d_in[19], *bs1 = (const float*)d_in[20];
    const float *Wc1 = (const float*)d_in[21], *bc1 = (const float*)d_in[22];
    const float *Wc2 = (const float*)d_in[23], *bc2 = (const float*)d_in[24];
    const float *Wc3 = (const float*)d_in[25], *bc3 = (const float*)d_in[26];

    const int n = in_sizes[0] / 2;
    const int E = in_sizes[2];

    float *Q, *K, *V, *Ha, *Hb, *alpha, *den;
    int *src, *dst;
    cudaGetSymbolAddress((void**)&Q,     g_Q);
    cudaGetSymbolAddress((void**)&K,     g_K);
    cudaGetSymbolAddress((void**)&V,     g_V);
    cudaGetSymbolAddress((void**)&Ha,    g_Ha);
    cudaGetSymbolAddress((void**)&Hb,    g_Hb);
    cudaGetSymbolAddress((void**)&alpha, g_alpha);
    cudaGetSymbolAddress((void**)&den,   g_den);
    cudaGetSymbolAddress((void**)&src,   g_src);
    cudaGetSymbolAddress((void**)&dst,   g_dst);

    const int TB = 256;
    dim3 edgeGrid((E + 7) / 8);
    dim3 tcGrid((n + 63) / 64);

    const int SM128 = (4 * 16 * 32 * 4 + 16 * 16 * 32 * 2) * 4;  // 98304 B
    const int SM64  = (4 * 16 * 32 * 4 + 16 *  8 * 32 * 2) * 4;  // 65536 B
    cudaFuncSetAttribute(gemm_tc<128, true,  false>, cudaFuncAttributeMaxDynamicSharedMemorySize, SM128);
    cudaFuncSetAttribute(gemm_tc<128, true,  true >, cudaFuncAttributeMaxDynamicSharedMemorySize, SM128);
    cudaFuncSetAttribute(gemm_tc<64,  false, true >, cudaFuncAttributeMaxDynamicSharedMemorySize, SM64);

    convert_ei_kernel<<<(E + TB - 1) / TB, TB>>>(eiw, E, src, dst);

    // ---------------- layer 0 ----------------
    proj0_kernel<<<(n * HCD + TB - 1) / TB, TB>>>(x, Wq0, bq0, Wk0, bk0, Wv0, bv0,
                                                  Ws0, bs0, Q, K, V, Ha, n);
    init_den_kernel<<<(n * NH + TB - 1) / TB, TB>>>(den, n * NH);
    edge_alpha_kernel<<<edgeGrid, TB>>>(src, dst, ea, Q, K, We0, alpha, den, E);
    edge_aggr_kernel <<<edgeGrid, TB>>>(src, dst, ea, V, We0, alpha, den, Ha, E);

    // ---------------- layer 1 projections (input = relu(Ha)) ----------------
    gemm_tc<128, true, false><<<tcGrid, 128, SM128>>>(Ha, Wq1, bq1, Q,  n);
    gemm_tc<128, true, false><<<tcGrid, 128, SM128>>>(Ha, Wk1, bk1, K,  n);
    gemm_tc<128, true, false><<<tcGrid, 128, SM128>>>(Ha, Wv1, bv1, V,  n);
    gemm_tc<128, true, false><<<tcGrid, 128, SM128>>>(Ha, Ws1, bs1, Hb, n);

    init_den_kernel<<<(n * NH + TB - 1) / TB, TB>>>(den, n * NH);
    edge_alpha_kernel<<<edgeGrid, TB>>>(src, dst, ea, Q, K, We1, alpha, den, E);
    edge_aggr_kernel <<<edgeGrid, TB>>>(src, dst, ea, V, We1, alpha, den, Hb, E);

    // ---------------- classifier (input = relu(Hb)) ----------------
    gemm_tc<128, true,  true><<<tcGrid, 128, SM128>>>(Hb, Wc1, bc1, Q, n);  // Z1
    gemm_tc<64,  false, true><<<tcGrid, 128, SM64 >>>(Q,  Wc2, bc2, K, n);  // Z2
    final_kernel<<<(n + TB - 1) / TB, TB>>>(K, Wc3, bc3, (float*)d_out, n);
}

// round 4
// speedup vs baseline: 1.0393x; 1.0129x over previous
#include <cuda_runtime.h>
#include <math.h>

#define NMAX 100000
#define EMAX 800000
#define HCD  128     // H*C = 4*32
#define NH   4       // heads

// ---------------- scratch ----------------------------------------------------
__device__ float g_Q [(size_t)NMAX * HCD];
__device__ float g_K [(size_t)NMAX * HCD];
__device__ float g_V [(size_t)NMAX * HCD];
__device__ float g_Ha[(size_t)NMAX * HCD];
__device__ float g_Hb[(size_t)NMAX * HCD];
__device__ float g_alpha[(size_t)EMAX * NH];
__device__ int   g_src[EMAX];
__device__ int   g_dst[EMAX];
__device__ int   g_deg[NMAX + 1];
__device__ int   g_rowptr[NMAX + 1];
__device__ int   g_fill[NMAX];
__device__ int   g_csrc[EMAX];
__device__ float g_cea[EMAX];

// ---------------- helpers -----------------------------------------------------
__device__ __forceinline__ unsigned tf32cvt(float f) {
    unsigned u;
    asm("cvt.rna.tf32.f32 %0, %1;" : "=r"(u) : "f"(f));
    return u;
}

__device__ __forceinline__ void mma_tf32(float* c, const unsigned* a, const unsigned* b) {
    asm volatile(
        "mma.sync.aligned.m16n8k8.row.col.f32.tf32.tf32.f32 "
        "{%0,%1,%2,%3}, {%4,%5,%6,%7}, {%8,%9}, {%0,%1,%2,%3};"
        : "+f"(c[0]), "+f"(c[1]), "+f"(c[2]), "+f"(c[3])
        : "r"(a[0]), "r"(a[1]), "r"(a[2]), "r"(a[3]), "r"(b[0]), "r"(b[1]));
}

// fragment-order store into A smem tile (row 0..63 local, k 0..127)
__device__ __forceinline__ void storeAfrag(float* sA, int row, int k, float v) {
    int w = row >> 4, r = row & 15, s = k >> 3, kk = k & 7;
    int lane = ((r & 7) << 2) | (kk & 3);
    int ii   = (r >> 3) | ((kk >> 2) << 1);
    sA[(((w * 16 + s) * 32) + lane) * 4 + ii] = v;
}

// ---------------- edge_index normalization + degree histogram ------------------
__global__ void convert_ei_kernel(const int* __restrict__ p, int E,
                                  int* __restrict__ src, int* __restrict__ dst,
                                  int* __restrict__ deg) {
    __shared__ int s_is64;
    if (threadIdx.x == 0) {
        int is64 = 1;
        for (int i = 0; i < 64; i++)
            if (p[2 * i + 1] != 0) { is64 = 0; break; }
        s_is64 = is64;
    }
    __syncthreads();
    const int is64 = s_is64;
    int e = blockIdx.x * blockDim.x + threadIdx.x;
    if (e >= E) return;
    int s, d;
    if (is64) { s = p[2 * e]; d = p[2 * (E + e)]; }
    else      { s = p[e];     d = p[E + e]; }
    src[e] = s; dst[e] = d;
    atomicAdd(&deg[d], 1);
}

// ---------------- single-block exclusive scan over degrees ---------------------
__global__ void scan_kernel(const int* __restrict__ deg, int* __restrict__ rowptr, int n) {
    __shared__ int sm[1024];
    int tid = threadIdx.x;
    int chunk = (n + 1023) >> 10;
    int start = tid * chunk;
    int end = min(start + chunk, n);
    int sum = 0;
    for (int i = start; i < end; i++) sum += deg[i];
    sm[tid] = sum;
    __syncthreads();
    for (int d = 1; d < 1024; d <<= 1) {
        int v = (tid >= d) ? sm[tid - d] : 0;
        __syncthreads();
        sm[tid] += v;
        __syncthreads();
    }
    int off = sm[tid] - sum;   // exclusive
    for (int i = start; i < end; i++) { rowptr[i] = off; off += deg[i]; }
    if (tid == 1023) rowptr[n] = off;
}

// ---------------- scatter edges into CSR order ---------------------------------
__global__ void scatter_kernel(const int* __restrict__ src, const int* __restrict__ dst,
                               const float* __restrict__ ea,
                               const int* __restrict__ rowptr, int* __restrict__ fill,
                               int* __restrict__ csrc, float* __restrict__ cea, int E) {
    int e = blockIdx.x * blockDim.x + threadIdx.x;
    if (e >= E) return;
    int d = dst[e];
    int pos = rowptr[d] + atomicAdd(&fill[d], 1);
    csrc[pos] = src[e];
    cea[pos]  = ea[e];
}

// ---------------- layer-0 projection (input dim = 2) ---------------------------
__global__ void proj0_kernel(const float* __restrict__ x,
                             const float* __restrict__ Wq, const float* __restrict__ bq,
                             const float* __restrict__ Wk, const float* __restrict__ bk,
                             const float* __restrict__ Wv, const float* __restrict__ bv,
                             const float* __restrict__ Ws, const float* __restrict__ bs,
                             float* __restrict__ Q, float* __restrict__ K,
                             float* __restrict__ V, float* __restrict__ S, int n) {
    int i = blockIdx.x * blockDim.x + threadIdx.x;
    if (i >= n * HCD) return;
    int node = i >> 7;
    int c    = i & (HCD - 1);
    float x0 = __ldg(&x[node * 2 + 0]);
    float x1 = __ldg(&x[node * 2 + 1]);
    Q[i] = fmaf(x0, __ldg(&Wq[c]), fmaf(x1, __ldg(&Wq[HCD + c]), __ldg(&bq[c])));
    K[i] = fmaf(x0, __ldg(&Wk[c]), fmaf(x1, __ldg(&Wk[HCD + c]), __ldg(&bk[c])));
    V[i] = fmaf(x0, __ldg(&Wv[c]), fmaf(x1, __ldg(&Wv[HCD + c]), __ldg(&bv[c])));
    S[i] = fmaf(x0, __ldg(&Ws[c]), fmaf(x1, __ldg(&Ws[HCD + c]), __ldg(&bs[c])));
}

// ---------------- fused per-layer edge pass (warp per dst node) ----------------
// H holds the skip term on entry; on exit H = skip + attention aggregation.
__global__ __launch_bounds__(256)
void tconv_kernel(const int* __restrict__ rowptr, const int* __restrict__ csrc,
                  const float* __restrict__ cea,
                  const float* __restrict__ Q, const float* __restrict__ K,
                  const float* __restrict__ V, const float* __restrict__ We,
                  float* __restrict__ H, float* __restrict__ abuf, int n) {
    int node = (blockIdx.x * blockDim.x + threadIdx.x) >> 5;
    if (node >= n) return;
    int lane = threadIdx.x & 31;
    int r0 = __ldg(&rowptr[node]);
    int r1 = __ldg(&rowptr[node + 1]);
    int c0 = lane * 4;
    int h  = lane >> 3;

    float4 q = *(const float4*)(Q + (size_t)node * HCD + c0);
    float4 w = *(const float4*)(We + c0);

    float den = 0.f;
    for (int e = r0; e < r1; e++) {
        int   src = __ldg(&csrc[e]);
        float eat = __ldg(&cea[e]);
        float4 k = *(const float4*)(K + (size_t)src * HCD + c0);
        float p = q.x * fmaf(eat, w.x, k.x)
                + q.y * fmaf(eat, w.y, k.y)
                + q.z * fmaf(eat, w.z, k.z)
                + q.w * fmaf(eat, w.w, k.w);
        p += __shfl_xor_sync(0xffffffffu, p, 1);
        p += __shfl_xor_sync(0xffffffffu, p, 2);
        p += __shfl_xor_sync(0xffffffffu, p, 4);   // all 8 lanes of head group have sum
        float ex = expf(p * 0.17677669529663687f); // 1/sqrt(32)
        den += ex;
        if ((lane & 7) == 0) abuf[(size_t)e * NH + h] = ex;
    }
    float invden = 1.f / (den + 1e-16f);

    float4 acc = *(const float4*)(H + (size_t)node * HCD + c0);  // skip term
    for (int e = r0; e < r1; e++) {
        int   src = __ldg(&csrc[e]);
        float eat = __ldg(&cea[e]);
        float ex  = __ldg(&abuf[(size_t)e * NH + h]);
        float wgt = ex * invden;
        float4 v = *(const float4*)(V + (size_t)src * HCD + c0);
        acc.x = fmaf(fmaf(eat, w.x, v.x), wgt, acc.x);
        acc.y = fmaf(fmaf(eat, w.y, v.y), wgt, acc.y);
        acc.z = fmaf(fmaf(eat, w.z, v.z), wgt, acc.z);
        acc.w = fmaf(fmaf(eat, w.w, v.w), wgt, acc.w);
    }
    *(float4*)(H + (size_t)node * HCD + c0) = acc;
}

// ---------------- shared GEMM building blocks (3xTF32) --------------------------
// A tile: 64 rows x 128 k, fragment order, float. 4 warps, 16 rows/warp.
template<bool RIN>
__device__ __forceinline__ void fillA(float* sA, const float* __restrict__ X,
                                      int node0, int n, int tid) {
    for (int base = tid * 4; base < 64 * 128; base += 128 * 4) {
        int row  = base >> 7;
        int k0   = base & 127;
        int node = node0 + row;
        float4 v = make_float4(0.f, 0.f, 0.f, 0.f);
        if (node < n) v = *(const float4*)(X + (size_t)node * 128 + k0);
        if (RIN) {
            v.x = fmaxf(v.x, 0.f); v.y = fmaxf(v.y, 0.f);
            v.z = fmaxf(v.z, 0.f); v.w = fmaxf(v.w, 0.f);
        }
        storeAfrag(sA, row, k0 + 0, v.x);
        storeAfrag(sA, row, k0 + 1, v.y);
        storeAfrag(sA, row, k0 + 2, v.z);
        storeAfrag(sA, row, k0 + 3, v.w);
    }
}

template<int NC>
__device__ __forceinline__ void fillB(float* sB, const float* __restrict__ W, int tid) {
    constexpr int JT = NC / 8;
    for (int base = tid * 4; base < 128 * NC; base += 128 * 4) {
        int k  = base / NC;
        int n0 = base % NC;
        float4 v = __ldg((const float4*)(W + (size_t)k * NC + n0));
        float vv[4] = {v.x, v.y, v.z, v.w};
        int s = k >> 3, kk = k & 7, ii = kk >> 2;
#pragma unroll
        for (int i = 0; i < 4; i++) {
            int nn = n0 + i, j = nn >> 3;
            int lane = ((nn & 7) << 2) | (kk & 3);
            sB[(((s * JT + j) * 32) + lane) * 2 + ii] = vv[i];
        }
    }
}

template<int JT>
__device__ __forceinline__ void computeTile(const float* sA, const float* sB,
                                            float acc[][4], int wid, int lane) {
#pragma unroll
    for (int s = 0; s < 16; s++) {
        float4 af = *(const float4*)&sA[(((wid * 16 + s) * 32) + lane) * 4];
        float afv[4] = {af.x, af.y, af.z, af.w};
        unsigned ahi[4], alo[4];
#pragma unroll
        for (int i = 0; i < 4; i++) {
            ahi[i] = tf32cvt(afv[i]);
            alo[i] = tf32cvt(afv[i] - __uint_as_float(ahi[i]));
        }
#pragma unroll
        for (int j = 0; j < JT; j++) {
            float2 bf = *(const float2*)&sB[(((s * JT + j) * 32) + lane) * 2];
            unsigned bhi[2], blo[2];
            bhi[0] = tf32cvt(bf.x); blo[0] = tf32cvt(bf.x - __uint_as_float(bhi[0]));
            bhi[1] = tf32cvt(bf.y); blo[1] = tf32cvt(bf.y - __uint_as_float(bhi[1]));
            mma_tf32(acc[j], ahi, bhi);
            mma_tf32(acc[j], alo, bhi);
            mma_tf32(acc[j], ahi, blo);
        }
    }
}

// ---------------- fused 4-projection GEMM (layer 1) ----------------------------
__global__ __launch_bounds__(128)
void gemm4_kernel(const float* __restrict__ X,
                  const float* __restrict__ W0, const float* __restrict__ b0, float* __restrict__ Y0,
                  const float* __restrict__ W1, const float* __restrict__ b1, float* __restrict__ Y1,
                  const float* __restrict__ W2, const float* __restrict__ b2, float* __restrict__ Y2,
                  const float* __restrict__ W3, const float* __restrict__ b3, float* __restrict__ Y3,
                  int n) {
    extern __shared__ float smem[];
    float* sA = smem;                  // 8192 floats
    float* sB = smem + 8192;           // 16384 floats (JT=16)
    const int tid = threadIdx.x;
    const int wid = tid >> 5, lane = tid & 31;
    const int node0 = blockIdx.x * 64;

    fillA<true>(sA, X, node0, n, tid);

    const float* Wm[4] = {W0, W1, W2, W3};
    const float* bm[4] = {b0, b1, b2, b3};
    float*       Ym[4] = {Y0, Y1, Y2, Y3};

    for (int m = 0; m < 4; m++) {
        __syncthreads();               // prior compute done reading sB (and sA ready)
        fillB<128>(sB, Wm[m], tid);
        __syncthreads();

        float acc[16][4];
#pragma unroll
        for (int j = 0; j < 16; j++) {
            float bb0 = __ldg(&bm[m][j * 8 + (lane & 3) * 2]);
            float bb1 = __ldg(&bm[m][j * 8 + (lane & 3) * 2 + 1]);
            acc[j][0] = bb0; acc[j][1] = bb1; acc[j][2] = bb0; acc[j][3] = bb1;
        }
        computeTile<16>(sA, sB, acc, wid, lane);

        int row0 = node0 + wid * 16 + (lane >> 2);
        int row1 = row0 + 8;
        float* Y = Ym[m];
#pragma unroll
        for (int j = 0; j < 16; j++) {
            int col = j * 8 + (lane & 3) * 2;
            if (row0 < n) *(float2*)(Y + (size_t)row0 * 128 + col) = make_float2(acc[j][0], acc[j][1]);
            if (row1 < n) *(float2*)(Y + (size_t)row1 * 128 + col) = make_float2(acc[j][2], acc[j][3]);
        }
    }
}

// ---------------- fused classifier: relu(Hb)@Wc1+b1 -> relu -> @Wc2+b2 -> relu -> @Wc3+b3
__global__ __launch_bounds__(128)
void classifier_kernel(const float* __restrict__ X,
                       const float* __restrict__ Wc1, const float* __restrict__ bc1,
                       const float* __restrict__ Wc2, const float* __restrict__ bc2,
                       const float* __restrict__ Wc3, const float* __restrict__ bc3,
                       float* __restrict__ out, int n) {
    extern __shared__ float smem[];
    float* sA = smem;
    float* sB = smem + 8192;
    const int tid = threadIdx.x;
    const int wid = tid >> 5, lane = tid & 31;
    const int node0 = blockIdx.x * 64;

    fillA<true>(sA, X, node0, n, tid);
    fillB<128>(sB, Wc1, tid);
    __syncthreads();

    // ---- stage 1: Z1 = relu(X @ Wc1 + bc1), 128 cols ----
    float acc[16][4];
#pragma unroll
    for (int j = 0; j < 16; j++) {
        float bb0 = __ldg(&bc1[j * 8 + (lane & 3) * 2]);
        float bb1 = __ldg(&bc1[j * 8 + (lane & 3) * 2 + 1]);
        acc[j][0] = bb0; acc[j][1] = bb1; acc[j][2] = bb0; acc[j][3] = bb1;
    }
    computeTile<16>(sA, sB, acc, wid, lane);

    // write Z1 back into sA in fragment order (own warp's region only)
    {
        int lr0 = wid * 16 + (lane >> 2);
        int lr1 = lr0 + 8;
#pragma unroll
        for (int j = 0; j < 16; j++) {
            int col = j * 8 + (lane & 3) * 2;
            storeAfrag(sA, lr0, col,     fmaxf(acc[j][0], 0.f));
            storeAfrag(sA, lr0, col + 1, fmaxf(acc[j][1], 0.f));
            storeAfrag(sA, lr1, col,     fmaxf(acc[j][2], 0.f));
            storeAfrag(sA, lr1, col + 1, fmaxf(acc[j][3], 0.f));
        }
    }
    __syncthreads();
    fillB<64>(sB, Wc2, tid);
    __syncthreads();

    // ---- stage 2: Z2 = relu(Z1 @ Wc2 + bc2), 64 cols ----
    float acc2[8][4];
#pragma unroll
    for (int j = 0; j < 8; j++) {
        float bb0 = __ldg(&bc2[j * 8 + (lane & 3) * 2]);
        float bb1 = __ldg(&bc2[j * 8 + (lane & 3) * 2 + 1]);
        acc2[j][0] = bb0; acc2[j][1] = bb1; acc2[j][2] = bb0; acc2[j][3] = bb1;
    }
    computeTile<8>(sA, sB, acc2, wid, lane);

    // ---- stage 3: out = relu(Z2) @ Wc3 + bc3 ----
    float p0 = 0.f, p1 = 0.f;
#pragma unroll
    for (int j = 0; j < 8; j++) {
        int c = j * 8 + (lane & 3) * 2;
        float w0 = __ldg(&Wc3[c]), w1 = __ldg(&Wc3[c + 1]);
        p0 += fmaxf(acc2[j][0], 0.f) * w0 + fmaxf(acc2[j][1], 0.f) * w1;
        p1 += fmaxf(acc2[j][2], 0.f) * w0 + fmaxf(acc2[j][3], 0.f) * w1;
    }
    p0 += __shfl_xor_sync(0xffffffffu, p0, 1);
    p0 += __shfl_xor_sync(0xffffffffu, p0, 2);
    p1 += __shfl_xor_sync(0xffffffffu, p1, 1);
    p1 += __shfl_xor_sync(0xffffffffu, p1, 2);

    if ((lane & 3) == 0) {
        float bv = __ldg(&bc3[0]);
        int row0 = node0 + wid * 16 + (lane >> 2);
        int row1 = row0 + 8;
        if (row0 < n) out[row0] = p0 + bv;
        if (row1 < n) out[row1] = p1 + bv;
    }
}

// ---------------- launch ---------------------------------------------------------
extern "C" void kernel_launch(void* const* d_in, const int* in_sizes, int n_in,
                              void* d_out, int out_size) {
    const float* x   = (const float*)d_in[0];
    const int*   eiw = (const int*)d_in[1];
    const float* ea  = (const float*)d_in[2];
    const float *Wq0 = (const float*)d_in[3],  *bq0 = (const float*)d_in[4];
    const float *Wk0 = (const float*)d_in[5],  *bk0 = (const float*)d_in[6];
    const float *Wv0 = (const float*)d_in[7],  *bv0 = (const float*)d_in[8];
    const float *We0 = (const float*)d_in[9];
    const float *Ws0 = (const float*)d_in[10], *bs0 = (const float*)d_in[11];
    const float *Wq1 = (const float*)d_in[12], *bq1 = (const float*)d_in[13];
    const float *Wk1 = (const float*)d_in[14], *bk1 = (const float*)d_in[15];
    const float *Wv1 = (const float*)d_in[16], *bv1 = (const float*)d_in[17];
    const float *We1 = (const float*)d_in[18];
    const float *Ws1 = (const float*)d_in[19], *bs1 = (const float*)d_in[20];
    const float *Wc1 = (const float*)d_in[21], *bc1 = (const float*)d_in[22];
    const float *Wc2 = (const float*)d_in[23], *bc2 = (const float*)d_in[24];
    const float *Wc3 = (const float*)d_in[25], *bc3 = (const float*)d_in[26];

    const int n = in_sizes[0] / 2;
    const int E = in_sizes[2];

    float *Q, *K, *V, *Ha, *Hb, *abuf, *cea;
    int *src, *dst, *deg, *rowptr, *fill, *csrc;
    cudaGetSymbolAddress((void**)&Q,      g_Q);
    cudaGetSymbolAddress((void**)&K,      g_K);
    cudaGetSymbolAddress((void**)&V,      g_V);
    cudaGetSymbolAddress((void**)&Ha,     g_Ha);
    cudaGetSymbolAddress((void**)&Hb,     g_Hb);
    cudaGetSymbolAddress((void**)&abuf,   g_alpha);
    cudaGetSymbolAddress((void**)&src,    g_src);
    cudaGetSymbolAddress((void**)&dst,    g_dst);
    cudaGetSymbolAddress((void**)&deg,    g_deg);
    cudaGetSymbolAddress((void**)&rowptr, g_rowptr);
    cudaGetSymbolAddress((void**)&fill,   g_fill);
    cudaGetSymbolAddress((void**)&csrc,   g_csrc);
    cudaGetSymbolAddress((void**)&cea,    g_cea);

    const int TB = 256;
    dim3 edgeGrid((E + TB - 1) / TB);
    dim3 nodeWarpGrid((n * 32 + TB - 1) / TB);
    dim3 tileGrid((n + 63) / 64);

    const int SMEM = (8192 + 16384) * 4;   // 98304 B
    cudaFuncSetAttribute(gemm4_kernel,      cudaFuncAttributeMaxDynamicSharedMemorySize, SMEM);
    cudaFuncSetAttribute(classifier_kernel, cudaFuncAttributeMaxDynamicSharedMemorySize, SMEM);

    // ---- CSR build ----
    cudaMemsetAsync(deg,  0, (n + 1) * sizeof(int));
    cudaMemsetAsync(fill, 0, n * sizeof(int));
    convert_ei_kernel<<<edgeGrid, TB>>>(eiw, E, src, dst, deg);
    scan_kernel<<<1, 1024>>>(deg, rowptr, n);
    scatter_kernel<<<edgeGrid, TB>>>(src, dst, ea, rowptr, fill, csrc, cea, E);

    // ---- layer 0 ----
    proj0_kernel<<<(n * HCD + TB - 1) / TB, TB>>>(x, Wq0, bq0, Wk0, bk0, Wv0, bv0,
                                                  Ws0, bs0, Q, K, V, Ha, n);
    tconv_kernel<<<nodeWarpGrid, TB>>>(rowptr, csrc, cea, Q, K, V, We0, Ha, abuf, n);

    // ---- layer 1 ----
    gemm4_kernel<<<tileGrid, 128, SMEM>>>(Ha,
                                          Wq1, bq1, Q,
                                          Wk1, bk1, K,
                                          Wv1, bv1, V,
                                          Ws1, bs1, Hb, n);
    tconv_kernel<<<nodeWarpGrid, TB>>>(rowptr, csrc, cea, Q, K, V, We1, Hb, abuf, n);

    // ---- classifier ----
    classifier_kernel<<<tileGrid, 128, SMEM>>>(Hb, Wc1, bc1, Wc2, bc2, Wc3, bc3,
                                               (float*)d_out, n);
}

// round 5
// speedup vs baseline: 1.0479x; 1.0083x over previous
#include <cuda_runtime.h>
#include <math.h>

#define NMAX 100000
#define EMAX 800000
#define HCD  128     // H*C = 4*32
#define NH   4       // heads

// ---------------- scratch ----------------------------------------------------
__device__ float g_Q [(size_t)NMAX * HCD];
__device__ float g_K [(size_t)NMAX * HCD];
__device__ float g_V [(size_t)NMAX * HCD];
__device__ float g_Ha[(size_t)NMAX * HCD];
__device__ float g_Hb[(size_t)NMAX * HCD];
__device__ int   g_src[EMAX];
__device__ int   g_dst[EMAX];
__device__ int   g_deg[NMAX + 1];
__device__ int   g_rowptr[NMAX + 1];
__device__ int   g_fill[NMAX];
__device__ int   g_csrc[EMAX];
__device__ float g_cea[EMAX];

// ---------------- helpers -----------------------------------------------------
__device__ __forceinline__ unsigned tf32cvt(float f) {
    unsigned u;
    asm("cvt.rna.tf32.f32 %0, %1;" : "=r"(u) : "f"(f));
    return u;
}

__device__ __forceinline__ void mma_tf32(float* c, const unsigned* a, const unsigned* b) {
    asm volatile(
        "mma.sync.aligned.m16n8k8.row.col.f32.tf32.tf32.f32 "
        "{%0,%1,%2,%3}, {%4,%5,%6,%7}, {%8,%9}, {%0,%1,%2,%3};"
        : "+f"(c[0]), "+f"(c[1]), "+f"(c[2]), "+f"(c[3])
        : "r"(a[0]), "r"(a[1]), "r"(a[2]), "r"(a[3]), "r"(b[0]), "r"(b[1]));
}

// fragment-order store into A smem tile (row 0..63 local, k 0..127)
__device__ __forceinline__ void storeAfrag(float* sA, int row, int k, float v) {
    int w = row >> 4, r = row & 15, s = k >> 3, kk = k & 7;
    int lane = ((r & 7) << 2) | (kk & 3);
    int ii   = (r >> 3) | ((kk >> 2) << 1);
    sA[(((w * 16 + s) * 32) + lane) * 4 + ii] = v;
}

// ---------------- edge_index normalization + degree histogram ------------------
__global__ void convert_ei_kernel(const int* __restrict__ p, int E,
                                  int* __restrict__ src, int* __restrict__ dst,
                                  int* __restrict__ deg) {
    __shared__ int s_is64;
    if (threadIdx.x == 0) {
        int is64 = 1;
        for (int i = 0; i < 64; i++)
            if (p[2 * i + 1] != 0) { is64 = 0; break; }
        s_is64 = is64;
    }
    __syncthreads();
    const int is64 = s_is64;
    int e = blockIdx.x * blockDim.x + threadIdx.x;
    if (e >= E) return;
    int s, d;
    if (is64) { s = p[2 * e]; d = p[2 * (E + e)]; }
    else      { s = p[e];     d = p[E + e]; }
    src[e] = s; dst[e] = d;
    atomicAdd(&deg[d], 1);
}

// ---------------- single-block exclusive scan over degrees ---------------------
__global__ void scan_kernel(const int* __restrict__ deg, int* __restrict__ rowptr, int n) {
    __shared__ int sm[1024];
    int tid = threadIdx.x;
    int chunk = (n + 1023) >> 10;
    int start = tid * chunk;
    int end = min(start + chunk, n);
    int sum = 0;
    for (int i = start; i < end; i++) sum += deg[i];
    sm[tid] = sum;
    __syncthreads();
    for (int d = 1; d < 1024; d <<= 1) {
        int v = (tid >= d) ? sm[tid - d] : 0;
        __syncthreads();
        sm[tid] += v;
        __syncthreads();
    }
    int off = sm[tid] - sum;   // exclusive
    for (int i = start; i < end; i++) { rowptr[i] = off; off += deg[i]; }
    if (tid == 1023) rowptr[n] = off;
}

// ---------------- scatter edges into CSR order ---------------------------------
__global__ void scatter_kernel(const int* __restrict__ src, const int* __restrict__ dst,
                               const float* __restrict__ ea,
                               const int* __restrict__ rowptr, int* __restrict__ fill,
                               int* __restrict__ csrc, float* __restrict__ cea, int E) {
    int e = blockIdx.x * blockDim.x + threadIdx.x;
    if (e >= E) return;
    int d = dst[e];
    int pos = rowptr[d] + atomicAdd(&fill[d], 1);
    csrc[pos] = src[e];
    cea[pos]  = ea[e];
}

// ---------------- layer-0 projection (input dim = 2) ---------------------------
__global__ void proj0_kernel(const float* __restrict__ x,
                             const float* __restrict__ Wq, const float* __restrict__ bq,
                             const float* __restrict__ Wk, const float* __restrict__ bk,
                             const float* __restrict__ Wv, const float* __restrict__ bv,
                             const float* __restrict__ Ws, const float* __restrict__ bs,
                             float* __restrict__ Q, float* __restrict__ K,
                             float* __restrict__ V, float* __restrict__ S, int n) {
    int i = blockIdx.x * blockDim.x + threadIdx.x;
    if (i >= n * HCD) return;
    int node = i >> 7;
    int c    = i & (HCD - 1);
    float x0 = __ldg(&x[node * 2 + 0]);
    float x1 = __ldg(&x[node * 2 + 1]);
    Q[i] = fmaf(x0, __ldg(&Wq[c]), fmaf(x1, __ldg(&Wq[HCD + c]), __ldg(&bq[c])));
    K[i] = fmaf(x0, __ldg(&Wk[c]), fmaf(x1, __ldg(&Wk[HCD + c]), __ldg(&bk[c])));
    V[i] = fmaf(x0, __ldg(&Wv[c]), fmaf(x1, __ldg(&Wv[HCD + c]), __ldg(&bv[c])));
    S[i] = fmaf(x0, __ldg(&Ws[c]), fmaf(x1, __ldg(&Ws[HCD + c]), __ldg(&bs[c])));
}

// ---------------- fused SINGLE-PASS edge kernel (warp per dst node) -------------
// out = skip + (sum_e ex_e * (v[src_e]+eat_e*We)) / (sum_e ex_e + 1e-16)
__global__ __launch_bounds__(256)
void tconv_kernel(const int* __restrict__ rowptr, const int* __restrict__ csrc,
                  const float* __restrict__ cea,
                  const float* __restrict__ Q, const float* __restrict__ K,
                  const float* __restrict__ V, const float* __restrict__ We,
                  float* __restrict__ H, int n) {
    int node = (blockIdx.x * blockDim.x + threadIdx.x) >> 5;
    if (node >= n) return;
    int lane = threadIdx.x & 31;
    int r0 = __ldg(&rowptr[node]);
    int r1 = __ldg(&rowptr[node + 1]);
    int c0 = lane * 4;

    float4 q = *(const float4*)(Q + (size_t)node * HCD + c0);
    float4 w = *(const float4*)(We + c0);

    float den = 0.f;
    float4 acc = make_float4(0.f, 0.f, 0.f, 0.f);

#pragma unroll 2
    for (int e = r0; e < r1; e++) {
        int   src = __ldg(&csrc[e]);
        float eat = __ldg(&cea[e]);
        const float4* krow = (const float4*)(K + (size_t)src * HCD);
        const float4* vrow = (const float4*)(V + (size_t)src * HCD);
        float4 k = krow[lane];          // independent loads -> both in flight
        float4 v = vrow[lane];

        float p = q.x * fmaf(eat, w.x, k.x)
                + q.y * fmaf(eat, w.y, k.y)
                + q.z * fmaf(eat, w.z, k.z)
                + q.w * fmaf(eat, w.w, k.w);
        p += __shfl_xor_sync(0xffffffffu, p, 1);
        p += __shfl_xor_sync(0xffffffffu, p, 2);
        p += __shfl_xor_sync(0xffffffffu, p, 4);   // uniform in 8-lane head group

        float ex = expf(p * 0.17677669529663687f); // 1/sqrt(32)
        den += ex;
        acc.x = fmaf(fmaf(eat, w.x, v.x), ex, acc.x);
        acc.y = fmaf(fmaf(eat, w.y, v.y), ex, acc.y);
        acc.z = fmaf(fmaf(eat, w.z, v.z), ex, acc.z);
        acc.w = fmaf(fmaf(eat, w.w, v.w), ex, acc.w);
    }

    float inv = 1.f / (den + 1e-16f);
    float4 out = *(const float4*)(H + (size_t)node * HCD + c0);  // skip term
    out.x = fmaf(acc.x, inv, out.x);
    out.y = fmaf(acc.y, inv, out.y);
    out.z = fmaf(acc.z, inv, out.z);
    out.w = fmaf(acc.w, inv, out.w);
    *(float4*)(H + (size_t)node * HCD + c0) = out;
}

// ---------------- shared GEMM building blocks (3xTF32) --------------------------
template<bool RIN>
__device__ __forceinline__ void fillA(float* sA, const float* __restrict__ X,
                                      int node0, int n, int tid) {
    for (int base = tid * 4; base < 64 * 128; base += 128 * 4) {
        int row  = base >> 7;
        int k0   = base & 127;
        int node = node0 + row;
        float4 v = make_float4(0.f, 0.f, 0.f, 0.f);
        if (node < n) v = *(const float4*)(X + (size_t)node * 128 + k0);
        if (RIN) {
            v.x = fmaxf(v.x, 0.f); v.y = fmaxf(v.y, 0.f);
            v.z = fmaxf(v.z, 0.f); v.w = fmaxf(v.w, 0.f);
        }
        storeAfrag(sA, row, k0 + 0, v.x);
        storeAfrag(sA, row, k0 + 1, v.y);
        storeAfrag(sA, row, k0 + 2, v.z);
        storeAfrag(sA, row, k0 + 3, v.w);
    }
}

template<int NC>
__device__ __forceinline__ void fillB(float* sB, const float* __restrict__ W, int tid) {
    constexpr int JT = NC / 8;
    for (int base = tid * 4; base < 128 * NC; base += 128 * 4) {
        int k  = base / NC;
        int n0 = base % NC;
        float4 v = __ldg((const float4*)(W + (size_t)k * NC + n0));
        float vv[4] = {v.x, v.y, v.z, v.w};
        int s = k >> 3, kk = k & 7, ii = kk >> 2;
#pragma unroll
        for (int i = 0; i < 4; i++) {
            int nn = n0 + i, j = nn >> 3;
            int lane = ((nn & 7) << 2) | (kk & 3);
            sB[(((s * JT + j) * 32) + lane) * 2 + ii] = vv[i];
        }
    }
}

template<int JT>
__device__ __forceinline__ void computeTile(const float* sA, const float* sB,
                                            float acc[][4], int wid, int lane) {
#pragma unroll
    for (int s = 0; s < 16; s++) {
        float4 af = *(const float4*)&sA[(((wid * 16 + s) * 32) + lane) * 4];
        float afv[4] = {af.x, af.y, af.z, af.w};
        unsigned ahi[4], alo[4];
#pragma unroll
        for (int i = 0; i < 4; i++) {
            ahi[i] = tf32cvt(afv[i]);
            alo[i] = tf32cvt(afv[i] - __uint_as_float(ahi[i]));
        }
#pragma unroll
        for (int j = 0; j < JT; j++) {
            float2 bf = *(const float2*)&sB[(((s * JT + j) * 32) + lane) * 2];
            unsigned bhi[2], blo[2];
            bhi[0] = tf32cvt(bf.x); blo[0] = tf32cvt(bf.x - __uint_as_float(bhi[0]));
            bhi[1] = tf32cvt(bf.y); blo[1] = tf32cvt(bf.y - __uint_as_float(bhi[1]));
            mma_tf32(acc[j], ahi, bhi);
            mma_tf32(acc[j], alo, bhi);
            mma_tf32(acc[j], ahi, blo);
        }
    }
}

// ---------------- fused 4-projection GEMM (layer 1) ----------------------------
__global__ __launch_bounds__(128)
void gemm4_kernel(const float* __restrict__ X,
                  const float* __restrict__ W0, const float* __restrict__ b0, float* __restrict__ Y0,
                  const float* __restrict__ W1, const float* __restrict__ b1, float* __restrict__ Y1,
                  const float* __restrict__ W2, const float* __restrict__ b2, float* __restrict__ Y2,
                  const float* __restrict__ W3, const float* __restrict__ b3, float* __restrict__ Y3,
                  int n) {
    extern __shared__ float smem[];
    float* sA = smem;                  // 8192 floats
    float* sB = smem + 8192;           // 16384 floats (JT=16)
    const int tid = threadIdx.x;
    const int wid = tid >> 5, lane = tid & 31;
    const int node0 = blockIdx.x * 64;

    fillA<true>(sA, X, node0, n, tid);

    const float* Wm[4] = {W0, W1, W2, W3};
    const float* bm[4] = {b0, b1, b2, b3};
    float*       Ym[4] = {Y0, Y1, Y2, Y3};

    for (int m = 0; m < 4; m++) {
        __syncthreads();
        fillB<128>(sB, Wm[m], tid);
        __syncthreads();

        float acc[16][4];
#pragma unroll
        for (int j = 0; j < 16; j++) {
            float bb0 = __ldg(&bm[m][j * 8 + (lane & 3) * 2]);
            float bb1 = __ldg(&bm[m][j * 8 + (lane & 3) * 2 + 1]);
            acc[j][0] = bb0; acc[j][1] = bb1; acc[j][2] = bb0; acc[j][3] = bb1;
        }
        computeTile<16>(sA, sB, acc, wid, lane);

        int row0 = node0 + wid * 16 + (lane >> 2);
        int row1 = row0 + 8;
        float* Y = Ym[m];
#pragma unroll
        for (int j = 0; j < 16; j++) {
            int col = j * 8 + (lane & 3) * 2;
            if (row0 < n) *(float2*)(Y + (size_t)row0 * 128 + col) = make_float2(acc[j][0], acc[j][1]);
            if (row1 < n) *(float2*)(Y + (size_t)row1 * 128 + col) = make_float2(acc[j][2], acc[j][3]);
        }
    }
}

// ---------------- fused classifier ---------------------------------------------
__global__ __launch_bounds__(128)
void classifier_kernel(const float* __restrict__ X,
                       const float* __restrict__ Wc1, const float* __restrict__ bc1,
                       const float* __restrict__ Wc2, const float* __restrict__ bc2,
                       const float* __restrict__ Wc3, const float* __restrict__ bc3,
                       float* __restrict__ out, int n) {
    extern __shared__ float smem[];
    float* sA = smem;
    float* sB = smem + 8192;
    const int tid = threadIdx.x;
    const int wid = tid >> 5, lane = tid & 31;
    const int node0 = blockIdx.x * 64;

    fillA<true>(sA, X, node0, n, tid);
    fillB<128>(sB, Wc1, tid);
    __syncthreads();

    float acc[16][4];
#pragma unroll
    for (int j = 0; j < 16; j++) {
        float bb0 = __ldg(&bc1[j * 8 + (lane & 3) * 2]);
        float bb1 = __ldg(&bc1[j * 8 + (lane & 3) * 2 + 1]);
        acc[j][0] = bb0; acc[j][1] = bb1; acc[j][2] = bb0; acc[j][3] = bb1;
    }
    computeTile<16>(sA, sB, acc, wid, lane);

    {
        int lr0 = wid * 16 + (lane >> 2);
        int lr1 = lr0 + 8;
#pragma unroll
        for (int j = 0; j < 16; j++) {
            int col = j * 8 + (lane & 3) * 2;
            storeAfrag(sA, lr0, col,     fmaxf(acc[j][0], 0.f));
            storeAfrag(sA, lr0, col + 1, fmaxf(acc[j][1], 0.f));
            storeAfrag(sA, lr1, col,     fmaxf(acc[j][2], 0.f));
            storeAfrag(sA, lr1, col + 1, fmaxf(acc[j][3], 0.f));
        }
    }
    __syncthreads();
    fillB<64>(sB, Wc2, tid);
    __syncthreads();

    float acc2[8][4];
#pragma unroll
    for (int j = 0; j < 8; j++) {
        float bb0 = __ldg(&bc2[j * 8 + (lane & 3) * 2]);
        float bb1 = __ldg(&bc2[j * 8 + (lane & 3) * 2 + 1]);
        acc2[j][0] = bb0; acc2[j][1] = bb1; acc2[j][2] = bb0; acc2[j][3] = bb1;
    }
    computeTile<8>(sA, sB, acc2, wid, lane);

    float p0 = 0.f, p1 = 0.f;
#pragma unroll
    for (int j = 0; j < 8; j++) {
        int c = j * 8 + (lane & 3) * 2;
        float w0 = __ldg(&Wc3[c]), w1 = __ldg(&Wc3[c + 1]);
        p0 += fmaxf(acc2[j][0], 0.f) * w0 + fmaxf(acc2[j][1], 0.f) * w1;
        p1 += fmaxf(acc2[j][2], 0.f) * w0 + fmaxf(acc2[j][3], 0.f) * w1;
    }
    p0 += __shfl_xor_sync(0xffffffffu, p0, 1);
    p0 += __shfl_xor_sync(0xffffffffu, p0, 2);
    p1 += __shfl_xor_sync(0xffffffffu, p1, 1);
    p1 += __shfl_xor_sync(0xffffffffu, p1, 2);

    if ((lane & 3) == 0) {
        float bv = __ldg(&bc3[0]);
        int row0 = node0 + wid * 16 + (lane >> 2);
        int row1 = row0 + 8;
        if (row0 < n) out[row0] = p0 + bv;
        if (row1 < n) out[row1] = p1 + bv;
    }
}

// ---------------- launch ---------------------------------------------------------
extern "C" void kernel_launch(void* const* d_in, const int* in_sizes, int n_in,
                              void* d_out, int out_size) {
    const float* x   = (const float*)d_in[0];
    const int*   eiw = (const int*)d_in[1];
    const float* ea  = (const float*)d_in[2];
    const float *Wq0 = (const float*)d_in[3],  *bq0 = (const float*)d_in[4];
    const float *Wk0 = (const float*)d_in[5],  *bk0 = (const float*)d_in[6];
    const float *Wv0 = (const float*)d_in[7],  *bv0 = (const float*)d_in[8];
    const float *We0 = (const float*)d_in[9];
    const float *Ws0 = (const float*)d_in[10], *bs0 = (const float*)d_in[11];
    const float *Wq1 = (const float*)d_in[12], *bq1 = (const float*)d_in[13];
    const float *Wk1 = (const float*)d_in[14], *bk1 = (const float*)d_in[15];
    const float *Wv1 = (const float*)d_in[16], *bv1 = (const float*)d_in[17];
    const float *We1 = (const float*)d_in[18];
    const float *Ws1 = (const float*)d_in[19], *bs1 = (const float*)d_in[20];
    const float *Wc1 = (const float*)d_in[21], *bc1 = (const float*)d_in[22];
    const float *Wc2 = (const float*)d_in[23], *bc2 = (const float*)d_in[24];
    const float *Wc3 = (const float*)d_in[25], *bc3 = (const float*)d_in[26];

    const int n = in_sizes[0] / 2;
    const int E = in_sizes[2];

    float *Q, *K, *V, *Ha, *Hb, *cea;
    int *src, *dst, *deg, *rowptr, *fill, *csrc;
    cudaGetSymbolAddress((void**)&Q,      g_Q);
    cudaGetSymbolAddress((void**)&K,      g_K);
    cudaGetSymbolAddress((void**)&V,      g_V);
    cudaGetSymbolAddress((void**)&Ha,     g_Ha);
    cudaGetSymbolAddress((void**)&Hb,     g_Hb);
    cudaGetSymbolAddress((void**)&src,    g_src);
    cudaGetSymbolAddress((void**)&dst,    g_dst);
    cudaGetSymbolAddress((void**)&deg,    g_deg);
    cudaGetSymbolAddress((void**)&rowptr, g_rowptr);
    cudaGetSymbolAddress((void**)&fill,   g_fill);
    cudaGetSymbolAddress((void**)&csrc,   g_csrc);
    cudaGetSymbolAddress((void**)&cea,    g_cea);

    const int TB = 256;
    dim3 edgeGrid((E + TB - 1) / TB);
    dim3 nodeWarpGrid((n * 32 + TB - 1) / TB);
    dim3 tileGrid((n + 63) / 64);

    const int SMEM = (8192 + 16384) * 4;   // 98304 B
    cudaFuncSetAttribute(gemm4_kernel,      cudaFuncAttributeMaxDynamicSharedMemorySize, SMEM);
    cudaFuncSetAttribute(classifier_kernel, cudaFuncAttributeMaxDynamicSharedMemorySize, SMEM);

    // ---- CSR build ----
    cudaMemsetAsync(deg,  0, (n + 1) * sizeof(int));
    cudaMemsetAsync(fill, 0, n * sizeof(int));
    convert_ei_kernel<<<edgeGrid, TB>>>(eiw, E, src, dst, deg);
    scan_kernel<<<1, 1024>>>(deg, rowptr, n);
    scatter_kernel<<<edgeGrid, TB>>>(src, dst, ea, rowptr, fill, csrc, cea, E);

    // ---- layer 0 ----
    proj0_kernel<<<(n * HCD + TB - 1) / TB, TB>>>(x, Wq0, bq0, Wk0, bk0, Wv0, bv0,
                                                  Ws0, bs0, Q, K, V, Ha, n);
    tconv_kernel<<<nodeWarpGrid, TB>>>(rowptr, csrc, cea, Q, K, V, We0, Ha, n);

    // ---- layer 1 ----
    gemm4_kernel<<<tileGrid, 128, SMEM>>>(Ha,
                                          Wq1, bq1, Q,
                                          Wk1, bk1, K,
                                          Wv1, bv1, V,
                                          Ws1, bs1, Hb, n);
    tconv_kernel<<<nodeWarpGrid, TB>>>(rowptr, csrc, cea, Q, K, V, We1, Hb, n);

    // ---- classifier ----
    classifier_kernel<<<tileGrid, 128, SMEM>>>(Hb, Wc1, bc1, Wc2, bc2, Wc3, bc3,
                                               (float*)d_out, n);
}

// round 6
// speedup vs baseline: 1.1939x; 1.1393x over previous
#include <cuda_runtime.h>
#include <cuda_fp16.h>
#include <math.h>

#define NMAX 100000
#define EMAX 800000
#define HCD  128     // H*C = 4*32
#define NH   4       // heads

// ---------------- scratch ----------------------------------------------------
__device__ float  g_Q [(size_t)NMAX * HCD];
__device__ __half g_KV[(size_t)NMAX * 2 * HCD];   // per node: 128 K halfs, 128 V halfs
__device__ float  g_Ha[(size_t)NMAX * HCD];
__device__ float  g_Hb[(size_t)NMAX * HCD];
__device__ int    g_src[EMAX];
__device__ int    g_dst[EMAX];
__device__ int    g_deg[NMAX + 1];
__device__ int    g_rowptr[NMAX + 1];
__device__ int    g_fill[NMAX];
__device__ int    g_csrc[EMAX];
__device__ float  g_cea[EMAX];

// ---------------- helpers -----------------------------------------------------
__device__ __forceinline__ unsigned tf32cvt(float f) {
    unsigned u;
    asm("cvt.rna.tf32.f32 %0, %1;" : "=r"(u) : "f"(f));
    return u;
}

__device__ __forceinline__ void mma_tf32(float* c, const unsigned* a, const unsigned* b) {
    asm volatile(
        "mma.sync.aligned.m16n8k8.row.col.f32.tf32.tf32.f32 "
        "{%0,%1,%2,%3}, {%4,%5,%6,%7}, {%8,%9}, {%0,%1,%2,%3};"
        : "+f"(c[0]), "+f"(c[1]), "+f"(c[2]), "+f"(c[3])
        : "r"(a[0]), "r"(a[1]), "r"(a[2]), "r"(a[3]), "r"(b[0]), "r"(b[1]));
}

__device__ __forceinline__ void storeAfrag(float* sA, int row, int k, float v) {
    int w = row >> 4, r = row & 15, s = k >> 3, kk = k & 7;
    int lane = ((r & 7) << 2) | (kk & 3);
    int ii   = (r >> 3) | ((kk >> 2) << 1);
    sA[(((w * 16 + s) * 32) + lane) * 4 + ii] = v;
}

// ---------------- clear deg + fill ----------------------------------------------
__global__ void clear_kernel(int* __restrict__ deg, int* __restrict__ fill, int n) {
    int i = blockIdx.x * blockDim.x + threadIdx.x;
    if (i <= n) deg[i] = 0;
    if (i < n)  fill[i] = 0;
}

// ---------------- edge_index normalization + degree histogram -------------------
__global__ void convert_ei_kernel(const int* __restrict__ p, int E,
                                  int* __restrict__ src, int* __restrict__ dst,
                                  int* __restrict__ deg) {
    __shared__ int s_is64;
    if (threadIdx.x == 0) {
        int is64 = 1;
        for (int i = 0; i < 64; i++)
            if (p[2 * i + 1] != 0) { is64 = 0; break; }
        s_is64 = is64;
    }
    __syncthreads();
    const int is64 = s_is64;
    int e = blockIdx.x * blockDim.x + threadIdx.x;
    if (e >= E) return;
    int s, d;
    if (is64) { s = p[2 * e]; d = p[2 * (E + e)]; }
    else      { s = p[e];     d = p[E + e]; }
    src[e] = s; dst[e] = d;
    atomicAdd(&deg[d], 1);
}

// ---------------- single-block exclusive scan over degrees ----------------------
__global__ void scan_kernel(const int* __restrict__ deg, int* __restrict__ rowptr, int n) {
    __shared__ int sm[1024];
    int tid = threadIdx.x;
    int chunk = (n + 1023) >> 10;
    int start = tid * chunk;
    int end = min(start + chunk, n);
    int sum = 0;
    for (int i = start; i < end; i++) sum += deg[i];
    sm[tid] = sum;
    __syncthreads();
    for (int d = 1; d < 1024; d <<= 1) {
        int v = (tid >= d) ? sm[tid - d] : 0;
        __syncthreads();
        sm[tid] += v;
        __syncthreads();
    }
    int off = sm[tid] - sum;   // exclusive
    for (int i = start; i < end; i++) { rowptr[i] = off; off += deg[i]; }
    if (tid == 1023) rowptr[n] = off;
}

// ---------------- scatter edges into CSR order ----------------------------------
__global__ void scatter_kernel(const int* __restrict__ src, const int* __restrict__ dst,
                               const float* __restrict__ ea,
                               const int* __restrict__ rowptr, int* __restrict__ fill,
                               int* __restrict__ csrc, float* __restrict__ cea, int E) {
    int e = blockIdx.x * blockDim.x + threadIdx.x;
    if (e >= E) return;
    int d = dst[e];
    int pos = rowptr[d] + atomicAdd(&fill[d], 1);
    csrc[pos] = src[e];
    cea[pos]  = ea[e];
}

// ---------------- layer-0 projection (input dim = 2) ----------------------------
__global__ void proj0_kernel(const float* __restrict__ x,
                             const float* __restrict__ Wq, const float* __restrict__ bq,
                             const float* __restrict__ Wk, const float* __restrict__ bk,
                             const float* __restrict__ Wv, const float* __restrict__ bv,
                             const float* __restrict__ Ws, const float* __restrict__ bs,
                             float* __restrict__ Q, __half* __restrict__ KV,
                             float* __restrict__ S, int n) {
    int i = blockIdx.x * blockDim.x + threadIdx.x;
    if (i >= n * HCD) return;
    int node = i >> 7;
    int c    = i & (HCD - 1);
    float x0 = __ldg(&x[node * 2 + 0]);
    float x1 = __ldg(&x[node * 2 + 1]);
    float qv = fmaf(x0, __ldg(&Wq[c]), fmaf(x1, __ldg(&Wq[HCD + c]), __ldg(&bq[c])));
    float kv = fmaf(x0, __ldg(&Wk[c]), fmaf(x1, __ldg(&Wk[HCD + c]), __ldg(&bk[c])));
    float vv = fmaf(x0, __ldg(&Wv[c]), fmaf(x1, __ldg(&Wv[HCD + c]), __ldg(&bv[c])));
    float sv = fmaf(x0, __ldg(&Ws[c]), fmaf(x1, __ldg(&Ws[HCD + c]), __ldg(&bs[c])));
    Q[i] = qv;
    S[i] = sv;
    KV[(size_t)node * 256 + c]       = __float2half_rn(kv);
    KV[(size_t)node * 256 + 128 + c] = __float2half_rn(vv);
}

// ---------------- fused single-pass edge kernel (warp per dst node) --------------
__global__ __launch_bounds__(256)
void tconv_kernel(const int* __restrict__ rowptr, const int* __restrict__ csrc,
                  const float* __restrict__ cea,
                  const float* __restrict__ Q, const __half* __restrict__ KV,
                  const float* __restrict__ We,
                  float* __restrict__ H, int n) {
    int node = (blockIdx.x * blockDim.x + threadIdx.x) >> 5;
    if (node >= n) return;
    int lane = threadIdx.x & 31;
    int r0 = __ldg(&rowptr[node]);
    int r1 = __ldg(&rowptr[node + 1]);
    int c0 = lane * 4;

    float4 q = *(const float4*)(Q + (size_t)node * HCD + c0);
    float4 w = *(const float4*)(We + c0);

    float den = 0.f;
    float4 acc = make_float4(0.f, 0.f, 0.f, 0.f);

    int e = r0;
    for (; e + 2 <= r1; e += 2) {
        int   s0 = __ldg(&csrc[e]);
        int   s1 = __ldg(&csrc[e + 1]);
        float a0 = __ldg(&cea[e]);
        float a1 = __ldg(&cea[e + 1]);

        // independent gather chains (K+V per src, fp16)
        uint2 k0r = *(const uint2*)(KV + (size_t)s0 * 256 + c0);
        uint2 v0r = *(const uint2*)(KV + (size_t)s0 * 256 + 128 + c0);
        uint2 k1r = *(const uint2*)(KV + (size_t)s1 * 256 + c0);
        uint2 v1r = *(const uint2*)(KV + (size_t)s1 * 256 + 128 + c0);

        float2 k0a = __half22float2(*(__half2*)&k0r.x);
        float2 k0b = __half22float2(*(__half2*)&k0r.y);
        float2 k1a = __half22float2(*(__half2*)&k1r.x);
        float2 k1b = __half22float2(*(__half2*)&k1r.y);

        float p0 = q.x * fmaf(a0, w.x, k0a.x) + q.y * fmaf(a0, w.y, k0a.y)
                 + q.z * fmaf(a0, w.z, k0b.x) + q.w * fmaf(a0, w.w, k0b.y);
        float p1 = q.x * fmaf(a1, w.x, k1a.x) + q.y * fmaf(a1, w.y, k1a.y)
                 + q.z * fmaf(a1, w.z, k1b.x) + q.w * fmaf(a1, w.w, k1b.y);

        p0 += __shfl_xor_sync(0xffffffffu, p0, 1);
        p1 += __shfl_xor_sync(0xffffffffu, p1, 1);
        p0 += __shfl_xor_sync(0xffffffffu, p0, 2);
        p1 += __shfl_xor_sync(0xffffffffu, p1, 2);
        p0 += __shfl_xor_sync(0xffffffffu, p0, 4);
        p1 += __shfl_xor_sync(0xffffffffu, p1, 4);

        float ex0 = expf(p0 * 0.17677669529663687f);   // 1/sqrt(32)
        float ex1 = expf(p1 * 0.17677669529663687f);
        den += ex0 + ex1;

        float2 v0a = __half22float2(*(__half2*)&v0r.x);
        float2 v0b = __half22float2(*(__half2*)&v0r.y);
        float2 v1a = __half22float2(*(__half2*)&v1r.x);
        float2 v1b = __half22float2(*(__half2*)&v1r.y);

        acc.x = fmaf(fmaf(a0, w.x, v0a.x), ex0, fmaf(fmaf(a1, w.x, v1a.x), ex1, acc.x));
        acc.y = fmaf(fmaf(a0, w.y, v0a.y), ex0, fmaf(fmaf(a1, w.y, v1a.y), ex1, acc.y));
        acc.z = fmaf(fmaf(a0, w.z, v0b.x), ex0, fmaf(fmaf(a1, w.z, v1b.x), ex1, acc.z));
        acc.w = fmaf(fmaf(a0, w.w, v0b.y), ex0, fmaf(fmaf(a1, w.w, v1b.y), ex1, acc.w));
    }
    if (e < r1) {
        int   s0 = __ldg(&csrc[e]);
        float a0 = __ldg(&cea[e]);
        uint2 k0r = *(const uint2*)(KV + (size_t)s0 * 256 + c0);
        uint2 v0r = *(const uint2*)(KV + (size_t)s0 * 256 + 128 + c0);
        float2 k0a = __half22float2(*(__half2*)&k0r.x);
        float2 k0b = __half22float2(*(__half2*)&k0r.y);
        float p0 = q.x * fmaf(a0, w.x, k0a.x) + q.y * fmaf(a0, w.y, k0a.y)
                 + q.z * fmaf(a0, w.z, k0b.x) + q.w * fmaf(a0, w.w, k0b.y);
        p0 += __shfl_xor_sync(0xffffffffu, p0, 1);
        p0 += __shfl_xor_sync(0xffffffffu, p0, 2);
        p0 += __shfl_xor_sync(0xffffffffu, p0, 4);
        float ex0 = expf(p0 * 0.17677669529663687f);
        den += ex0;
        float2 v0a = __half22float2(*(__half2*)&v0r.x);
        float2 v0b = __half22float2(*(__half2*)&v0r.y);
        acc.x = fmaf(fmaf(a0, w.x, v0a.x), ex0, acc.x);
        acc.y = fmaf(fmaf(a0, w.y, v0a.y), ex0, acc.y);
        acc.z = fmaf(fmaf(a0, w.z, v0b.x), ex0, acc.z);
        acc.w = fmaf(fmaf(a0, w.w, v0b.y), ex0, acc.w);
    }

    float inv = 1.f / (den + 1e-16f);
    float4 out = *(const float4*)(H + (size_t)node * HCD + c0);  // skip term
    out.x = fmaf(acc.x, inv, out.x);
    out.y = fmaf(acc.y, inv, out.y);
    out.z = fmaf(acc.z, inv, out.z);
    out.w = fmaf(acc.w, inv, out.w);
    *(float4*)(H + (size_t)node * HCD + c0) = out;
}

// ---------------- shared GEMM building blocks (3xTF32) ---------------------------
template<bool RIN>
__device__ __forceinline__ void fillA(float* sA, const float* __restrict__ X,
                                      int node0, int n, int tid) {
    for (int base = tid * 4; base < 64 * 128; base += 128 * 4) {
        int row  = base >> 7;
        int k0   = base & 127;
        int node = node0 + row;
        float4 v = make_float4(0.f, 0.f, 0.f, 0.f);
        if (node < n) v = *(const float4*)(X + (size_t)node * 128 + k0);
        if (RIN) {
            v.x = fmaxf(v.x, 0.f); v.y = fmaxf(v.y, 0.f);
            v.z = fmaxf(v.z, 0.f); v.w = fmaxf(v.w, 0.f);
        }
        storeAfrag(sA, row, k0 + 0, v.x);
        storeAfrag(sA, row, k0 + 1, v.y);
        storeAfrag(sA, row, k0 + 2, v.z);
        storeAfrag(sA, row, k0 + 3, v.w);
    }
}

template<int NC>
__device__ __forceinline__ void fillB(float* sB, const float* __restrict__ W, int tid) {
    constexpr int JT = NC / 8;
    for (int base = tid * 4; base < 128 * NC; base += 128 * 4) {
        int k  = base / NC;
        int n0 = base % NC;
        float4 v = __ldg((const float4*)(W + (size_t)k * NC + n0));
        float vv[4] = {v.x, v.y, v.z, v.w};
        int s = k >> 3, kk = k & 7, ii = kk >> 2;
#pragma unroll
        for (int i = 0; i < 4; i++) {
            int nn = n0 + i, j = nn >> 3;
            int lane = ((nn & 7) << 2) | (kk & 3);
            sB[(((s * JT + j) * 32) + lane) * 2 + ii] = vv[i];
        }
    }
}

template<int JT>
__device__ __forceinline__ void computeTile(const float* sA, const float* sB,
                                            float acc[][4], int wid, int lane) {
#pragma unroll
    for (int s = 0; s < 16; s++) {
        float4 af = *(const float4*)&sA[(((wid * 16 + s) * 32) + lane) * 4];
        float afv[4] = {af.x, af.y, af.z, af.w};
        unsigned ahi[4], alo[4];
#pragma unroll
        for (int i = 0; i < 4; i++) {
            ahi[i] = tf32cvt(afv[i]);
            alo[i] = tf32cvt(afv[i] - __uint_as_float(ahi[i]));
        }
#pragma unroll
        for (int j = 0; j < JT; j++) {
            float2 bf = *(const float2*)&sB[(((s * JT + j) * 32) + lane) * 2];
            unsigned bhi[2], blo[2];
            bhi[0] = tf32cvt(bf.x); blo[0] = tf32cvt(bf.x - __uint_as_float(bhi[0]));
            bhi[1] = tf32cvt(bf.y); blo[1] = tf32cvt(bf.y - __uint_as_float(bhi[1]));
            mma_tf32(acc[j], ahi, bhi);
            mma_tf32(acc[j], alo, bhi);
            mma_tf32(acc[j], ahi, blo);
        }
    }
}

// ---------------- fused 4-projection GEMM (layer 1) ------------------------------
// m=0 -> Q (fp32), m=1 -> K (fp16 into KV), m=2 -> V (fp16 into KV), m=3 -> S (fp32)
__global__ __launch_bounds__(128)
void gemm4_kernel(const float* __restrict__ X,
                  const float* __restrict__ W0, const float* __restrict__ b0, float* __restrict__ Q,
                  const float* __restrict__ W1, const float* __restrict__ b1,
                  const float* __restrict__ W2, const float* __restrict__ b2, __half* __restrict__ KV,
                  const float* __restrict__ W3, const float* __restrict__ b3, float* __restrict__ S,
                  int n) {
    extern __shared__ float smem[];
    float* sA = smem;                  // 8192 floats
    float* sB = smem + 8192;           // 16384 floats (JT=16)
    const int tid = threadIdx.x;
    const int wid = tid >> 5, lane = tid & 31;
    const int node0 = blockIdx.x * 64;

    fillA<true>(sA, X, node0, n, tid);

    const float* Wm[4] = {W0, W1, W2, W3};
    const float* bm[4] = {b0, b1, b2, b3};

    for (int m = 0; m < 4; m++) {
        __syncthreads();
        fillB<128>(sB, Wm[m], tid);
        __syncthreads();

        float acc[16][4];
#pragma unroll
        for (int j = 0; j < 16; j++) {
            float bb0 = __ldg(&bm[m][j * 8 + (lane & 3) * 2]);
            float bb1 = __ldg(&bm[m][j * 8 + (lane & 3) * 2 + 1]);
            acc[j][0] = bb0; acc[j][1] = bb1; acc[j][2] = bb0; acc[j][3] = bb1;
        }
        computeTile<16>(sA, sB, acc, wid, lane);

        int row0 = node0 + wid * 16 + (lane >> 2);
        int row1 = row0 + 8;
        if (m == 0 || m == 3) {
            float* Y = (m == 0) ? Q : S;
#pragma unroll
            for (int j = 0; j < 16; j++) {
                int col = j * 8 + (lane & 3) * 2;
                if (row0 < n) *(float2*)(Y + (size_t)row0 * 128 + col) = make_float2(acc[j][0], acc[j][1]);
                if (row1 < n) *(float2*)(Y + (size_t)row1 * 128 + col) = make_float2(acc[j][2], acc[j][3]);
            }
        } else {
            int off = (m == 1) ? 0 : 128;
#pragma unroll
            for (int j = 0; j < 16; j++) {
                int col = j * 8 + (lane & 3) * 2;
                __half2 h0 = __floats2half2_rn(acc[j][0], acc[j][1]);
                __half2 h1 = __floats2half2_rn(acc[j][2], acc[j][3]);
                if (row0 < n) *(__half2*)(KV + (size_t)row0 * 256 + off + col) = h0;
                if (row1 < n) *(__half2*)(KV + (size_t)row1 * 256 + off + col) = h1;
            }
        }
    }
}

// ---------------- fused classifier ------------------------------------------------
__global__ __launch_bounds__(128)
void classifier_kernel(const float* __restrict__ X,
                       const float* __restrict__ Wc1, const float* __restrict__ bc1,
                       const float* __restrict__ Wc2, const float* __restrict__ bc2,
                       const float* __restrict__ Wc3, const float* __restrict__ bc3,
                       float* __restrict__ out, int n) {
    extern __shared__ float smem[];
    float* sA = smem;
    float* sB = smem + 8192;
    const int tid = threadIdx.x;
    const int wid = tid >> 5, lane = tid & 31;
    const int node0 = blockIdx.x * 64;

    fillA<true>(sA, X, node0, n, tid);
    fillB<128>(sB, Wc1, tid);
    __syncthreads();

    float acc[16][4];
#pragma unroll
    for (int j = 0; j < 16; j++) {
        float bb0 = __ldg(&bc1[j * 8 + (lane & 3) * 2]);
        float bb1 = __ldg(&bc1[j * 8 + (lane & 3) * 2 + 1]);
        acc[j][0] = bb0; acc[j][1] = bb1; acc[j][2] = bb0; acc[j][3] = bb1;
    }
    computeTile<16>(sA, sB, acc, wid, lane);

    {
        int lr0 = wid * 16 + (lane >> 2);
        int lr1 = lr0 + 8;
#pragma unroll
        for (int j = 0; j < 16; j++) {
            int col = j * 8 + (lane & 3) * 2;
            storeAfrag(sA, lr0, col,     fmaxf(acc[j][0], 0.f));
            storeAfrag(sA, lr0, col + 1, fmaxf(acc[j][1], 0.f));
            storeAfrag(sA, lr1, col,     fmaxf(acc[j][2], 0.f));
            storeAfrag(sA, lr1, col + 1, fmaxf(acc[j][3], 0.f));
        }
    }
    __syncthreads();
    fillB<64>(sB, Wc2, tid);
    __syncthreads();

    float acc2[8][4];
#pragma unroll
    for (int j = 0; j < 8; j++) {
        float bb0 = __ldg(&bc2[j * 8 + (lane & 3) * 2]);
        float bb1 = __ldg(&bc2[j * 8 + (lane & 3) * 2 + 1]);
        acc2[j][0] = bb0; acc2[j][1] = bb1; acc2[j][2] = bb0; acc2[j][3] = bb1;
    }
    computeTile<8>(sA, sB, acc2, wid, lane);

    float p0 = 0.f, p1 = 0.f;
#pragma unroll
    for (int j = 0; j < 8; j++) {
        int c = j * 8 + (lane & 3) * 2;
        float w0 = __ldg(&Wc3[c]), w1 = __ldg(&Wc3[c + 1]);
        p0 += fmaxf(acc2[j][0], 0.f) * w0 + fmaxf(acc2[j][1], 0.f) * w1;
        p1 += fmaxf(acc2[j][2], 0.f) * w0 + fmaxf(acc2[j][3], 0.f) * w1;
    }
    p0 += __shfl_xor_sync(0xffffffffu, p0, 1);
    p0 += __shfl_xor_sync(0xffffffffu, p0, 2);
    p1 += __shfl_xor_sync(0xffffffffu, p1, 1);
    p1 += __shfl_xor_sync(0xffffffffu, p1, 2);

    if ((lane & 3) == 0) {
        float bv = __ldg(&bc3[0]);
        int row0 = node0 + wid * 16 + (lane >> 2);
        int row1 = row0 + 8;
        if (row0 < n) out[row0] = p0 + bv;
        if (row1 < n) out[row1] = p1 + bv;
    }
}

// ---------------- launch -----------------------------------------------------------
extern "C" void kernel_launch(void* const* d_in, const int* in_sizes, int n_in,
                              void* d_out, int out_size) {
    const float* x   = (const float*)d_in[0];
    const int*   eiw = (const int*)d_in[1];
    const float* ea  = (const float*)d_in[2];
    const float *Wq0 = (const float*)d_in[3],  *bq0 = (const float*)d_in[4];
    const float *Wk0 = (const float*)d_in[5],  *bk0 = (const float*)d_in[6];
    const float *Wv0 = (const float*)d_in[7],  *bv0 = (const float*)d_in[8];
    const float *We0 = (const float*)d_in[9];
    const float *Ws0 = (const float*)d_in[10], *bs0 = (const float*)d_in[11];
    const float *Wq1 = (const float*)d_in[12], *bq1 = (const float*)d_in[13];
    const float *Wk1 = (const float*)d_in[14], *bk1 = (const float*)d_in[15];
    const float *Wv1 = (const float*)d_in[16], *bv1 = (const float*)d_in[17];
    const float *We1 = (const float*)d_in[18];
    const float *Ws1 = (const float*)d_in[19], *bs1 = (const float*)d_in[20];
    const float *Wc1 = (const float*)d_in[21], *bc1 = (const float*)d_in[22];
    const float *Wc2 = (const float*)d_in[23], *bc2 = (const float*)d_in[24];
    const float *Wc3 = (const float*)d_in[25], *bc3 = (const float*)d_in[26];

    const int n = in_sizes[0] / 2;
    const int E = in_sizes[2];

    float *Q, *Ha, *Hb, *cea;
    __half* KV;
    int *src, *dst, *deg, *rowptr, *fill, *csrc;
    cudaGetSymbolAddress((void**)&Q,      g_Q);
    cudaGetSymbolAddress((void**)&KV,     g_KV);
    cudaGetSymbolAddress((void**)&Ha,     g_Ha);
    cudaGetSymbolAddress((void**)&Hb,     g_Hb);
    cudaGetSymbolAddress((void**)&src,    g_src);
    cudaGetSymbolAddress((void**)&dst,    g_dst);
    cudaGetSymbolAddress((void**)&deg,    g_deg);
    cudaGetSymbolAddress((void**)&rowptr, g_rowptr);
    cudaGetSymbolAddress((void**)&fill,   g_fill);
    cudaGetSymbolAddress((void**)&csrc,   g_csrc);
    cudaGetSymbolAddress((void**)&cea,    g_cea);

    const int TB = 256;
    dim3 edgeGrid((E + TB - 1) / TB);
    dim3 nodeWarpGrid((n * 32 + TB - 1) / TB);
    dim3 tileGrid((n + 63) / 64);

    const int SMEM = (8192 + 16384) * 4;   // 98304 B
    cudaFuncSetAttribute(gemm4_kernel,      cudaFuncAttributeMaxDynamicSharedMemorySize, SMEM);
    cudaFuncSetAttribute(classifier_kernel, cudaFuncAttributeMaxDynamicSharedMemorySize, SMEM);

    // Launch order chosen so that tconv (layer 0) is the 6th launch -> ncu -s 5 -c 1
    clear_kernel  <<<(n + TB) / TB, TB>>>(deg, fill, n);                       // 1
    convert_ei_kernel<<<edgeGrid, TB>>>(eiw, E, src, dst, deg);                 // 2
    scan_kernel   <<<1, 1024>>>(deg, rowptr, n);                                // 3
    scatter_kernel<<<edgeGrid, TB>>>(src, dst, ea, rowptr, fill, csrc, cea, E); // 4
    proj0_kernel  <<<(n * HCD + TB - 1) / TB, TB>>>(x, Wq0, bq0, Wk0, bk0,      // 5
                                                    Wv0, bv0, Ws0, bs0, Q, KV, Ha, n);
    tconv_kernel  <<<nodeWarpGrid, TB>>>(rowptr, csrc, cea, Q, KV, We0, Ha, n); // 6  <- profiled
    gemm4_kernel  <<<tileGrid, 128, SMEM>>>(Ha,                                  // 7
                                            Wq1, bq1, Q,
                                            Wk1, bk1,
                                            Wv1, bv1, KV,
                                            Ws1, bs1, Hb, n);
    tconv_kernel  <<<nodeWarpGrid, TB>>>(rowptr, csrc, cea, Q, KV, We1, Hb, n); // 8
    classifier_kernel<<<tileGrid, 128, SMEM>>>(Hb, Wc1, bc1, Wc2, bc2, Wc3, bc3, // 9
                                               (float*)d_out, n);
}